// round 13
// baseline (speedup 1.0000x reference)
#include <cuda_runtime.h>
#include <cuda_fp16.h>
#include <cstdint>
#include <math.h>

#define NN 50000
#define EE 200000
#define SCAN_BS 512
#define SCAN_NB 98          // ceil(NN/512)

// weight-split packing offsets (elements) inside g_Wh / g_Wl
#define WOFF4 0
#define WOFF5 131072        // 128*1024
#define WOFF6 655360        // +1024*512
#define WTOT  786432        // +512*256

// ---------------- scratch (static device globals; allocation-free) ----------------
__device__ float g_bufA[(size_t)NN * 1024];
__device__ float g_bufB[(size_t)NN * 1024];
__device__ __half g_Ahi[(size_t)NN * 1024];
__device__ __half g_Alo[(size_t)NN * 1024];
__device__ __half g_Bhi[(size_t)NN * 1024];
__device__ __half g_Blo[(size_t)NN * 1024];
__device__ __half g_Wh[WTOT];
__device__ __half g_Wl[WTOT];
__device__ int   g_cnt[NN];
__device__ int   g_cur[NN];
__device__ int   g_off[NN + 1];
__device__ int   g_bsum[SCAN_NB];
__device__ float g_dis[NN];
__device__ int   g_src[EE];
__device__ float g_enrm[EE];

// ================= PTX helpers (arch-generic: sm_80+) =================
__device__ __forceinline__ uint32_t smem_to_u32(const void* p) {
    uint32_t a;
    asm("{ .reg .u64 t; cvta.to.shared.u64 t, %1; cvt.u32.u64 %0, t; }" : "=r"(a) : "l"(p));
    return a;
}
#define CP_ASYNC16(dst, src) \
    asm volatile("cp.async.cg.shared.global [%0], [%1], 16;" :: "r"(dst), "l"(src))
#define CP_COMMIT() asm volatile("cp.async.commit_group;" ::: "memory")
#define CP_WAIT(n)  asm volatile("cp.async.wait_group %0;" :: "n"(n) : "memory")
#define LDSM_X4(r0, r1, r2, r3, addr) \
    asm volatile("ldmatrix.sync.aligned.m8n8.x4.shared.b16 {%0,%1,%2,%3}, [%4];" \
        : "=r"(r0), "=r"(r1), "=r"(r2), "=r"(r3) : "r"(addr))
#define MMA_16816(c, a, b) \
    asm volatile("mma.sync.aligned.m16n8k16.row.col.f32.f16.f16.f32 " \
        "{%0,%1,%2,%3}, {%4,%5,%6,%7}, {%8,%9}, {%0,%1,%2,%3};" \
        : "+f"((c)[0]), "+f"((c)[1]), "+f"((c)[2]), "+f"((c)[3]) \
        : "r"((a)[0]), "r"((a)[1]), "r"((a)[2]), "r"((a)[3]), "r"((b)[0]), "r"((b)[1]))

// ================= CSR build =================
__global__ void k_zero2(int* __restrict__ a, int* __restrict__ b) {
    int i = blockIdx.x * blockDim.x + threadIdx.x;
    if (i < NN) { a[i] = 0; b[i] = 0; }
}
__global__ void k_cnt(const int* __restrict__ col, int* __restrict__ cnt) {
    int e = blockIdx.x * blockDim.x + threadIdx.x;
    if (e < EE) atomicAdd(&cnt[col[e]], 1);
}
__global__ void k_scan1(const int* __restrict__ cnt, int* __restrict__ off,
                        int* __restrict__ bsum) {
    __shared__ int sh[SCAN_BS];
    int tid = threadIdx.x;
    int i = blockIdx.x * SCAN_BS + tid;
    int v = (i < NN) ? cnt[i] : 0;
    sh[tid] = v;
    __syncthreads();
    #pragma unroll
    for (int d = 1; d < SCAN_BS; d <<= 1) {
        int t = (tid >= d) ? sh[tid - d] : 0;
        __syncthreads();
        sh[tid] += t;
        __syncthreads();
    }
    if (i < NN) off[i] = sh[tid] - v;          // exclusive
    if (tid == SCAN_BS - 1) bsum[blockIdx.x] = sh[tid];
}
__global__ void k_scan2(int* __restrict__ bsum) {
    __shared__ int sh[128];
    int tid = threadIdx.x;
    int v = (tid < SCAN_NB) ? bsum[tid] : 0;
    sh[tid] = v;
    __syncthreads();
    #pragma unroll
    for (int d = 1; d < 128; d <<= 1) {
        int t = (tid >= d) ? sh[tid - d] : 0;
        __syncthreads();
        sh[tid] += t;
        __syncthreads();
    }
    if (tid < SCAN_NB) bsum[tid] = sh[tid] - v;  // exclusive
}
// also computes dis = rsqrt(deg)
__global__ void k_scan3(int* __restrict__ off, const int* __restrict__ bsum,
                        const int* __restrict__ cnt, float* __restrict__ dis) {
    int i = blockIdx.x * blockDim.x + threadIdx.x;
    if (i < NN) {
        off[i] += bsum[i / SCAN_BS];
        dis[i] = rsqrtf((float)(cnt[i] + 1));
    }
    if (i == 0) off[NN] = EE;
}
__global__ void k_fill(const int* __restrict__ row, const int* __restrict__ col,
                       const float* __restrict__ dis, const int* __restrict__ off,
                       int* __restrict__ cur, int* __restrict__ src,
                       float* __restrict__ enrm) {
    int e = blockIdx.x * blockDim.x + threadIdx.x;
    if (e >= EE) return;
    int r = row[e], c = col[e];
    int pos = off[c] + atomicAdd(&cur[c], 1);
    src[pos] = r;
    enrm[pos] = dis[r] * dis[c];
}

// ================= fused CSR gather aggregation (big layers) =================
template <int F, bool BIAS, bool RELU, bool SPLIT>
__global__ void __launch_bounds__(256) k_gather4(
    const float4* __restrict__ h, const int* __restrict__ off,
    const int* __restrict__ src, const float* __restrict__ enrm,
    const float* __restrict__ dis, const float* __restrict__ bias,
    float4* __restrict__ outf, __half2* __restrict__ ohi, __half2* __restrict__ olo) {
    constexpr int FV = F / 4;
    int idx = blockIdx.x * blockDim.x + threadIdx.x;
    if (idx >= NN * FV) return;
    int i = idx / FV;
    int f4 = idx - i * FV;
    float d = dis[i];
    float s = d * d;
    float4 v = h[(size_t)i * FV + f4];
    float4 acc;
    acc.x = s * v.x; acc.y = s * v.y; acc.z = s * v.z; acc.w = s * v.w;
    int p0 = off[i], p1 = off[i + 1];
    for (int p = p0; p < p1; p++) {
        int sn = src[p];
        float w = enrm[p];
        float4 u = h[(size_t)sn * FV + f4];
        acc.x += w * u.x; acc.y += w * u.y; acc.z += w * u.z; acc.w += w * u.w;
    }
    if (BIAS) {
        const float4 bv = *(const float4*)(bias + f4 * 4);
        acc.x += bv.x; acc.y += bv.y; acc.z += bv.z; acc.w += bv.w;
    }
    if (RELU) {
        acc.x = fmaxf(acc.x, 0.f); acc.y = fmaxf(acc.y, 0.f);
        acc.z = fmaxf(acc.z, 0.f); acc.w = fmaxf(acc.w, 0.f);
    }
    if (SPLIT) {
        __half hx = __float2half(acc.x), hy = __float2half(acc.y);
        __half hz = __float2half(acc.z), hw = __float2half(acc.w);
        __half lx = __float2half(acc.x - __half2float(hx));
        __half ly = __float2half(acc.y - __half2float(hy));
        __half lz = __float2half(acc.z - __half2float(hz));
        __half lw = __float2half(acc.w - __half2float(hw));
        ohi[(size_t)idx * 2 + 0] = __halves2half2(hx, hy);
        ohi[(size_t)idx * 2 + 1] = __halves2half2(hz, hw);
        olo[(size_t)idx * 2 + 0] = __halves2half2(lx, ly);
        olo[(size_t)idx * 2 + 1] = __halves2half2(lz, lw);
    } else {
        outf[idx] = acc;
    }
}

// scalar variant for F=3 and F=2
template <int F, bool BIAS>
__global__ void k_gather1(const float* __restrict__ h, const int* __restrict__ off,
                          const int* __restrict__ src, const float* __restrict__ enrm,
                          const float* __restrict__ dis, const float* __restrict__ bias,
                          float* __restrict__ outf) {
    int idx = blockIdx.x * blockDim.x + threadIdx.x;
    if (idx >= NN * F) return;
    int i = idx / F;
    int f = idx - i * F;
    float d = dis[i];
    float acc = d * d * h[(size_t)i * F + f];
    int p0 = off[i], p1 = off[i + 1];
    for (int p = p0; p < p1; p++)
        acc += enrm[p] * h[(size_t)src[p] * F + f];
    if (BIAS) acc += bias[f];
    outf[idx] = acc;
}

// ================= fused gather+GEMM for small layers (FIN=64) =================
// out[128 rows/CTA, FOUT] = relu( Agg(h)[128,64] @ W[64,FOUT] + bias )
// Phase 1: CSR gather into padded smem; Phase 2: smem GEMM. All fp32.
#define FS_AROWS 128
#define FS_ASTR  65          // padded row stride (floats) -> conflict-free column reads
#define FS_ABYTES (FS_AROWS * FS_ASTR * 4)

template <int FOUT>
__global__ void __launch_bounds__(256) k_fused_small(
    const float4* __restrict__ h,       // [NN,16] float4 view of [NN,64]
    const int* __restrict__ off, const int* __restrict__ src,
    const float* __restrict__ enrm, const float* __restrict__ dis,
    const float* __restrict__ W,        // [64, FOUT] row-major
    const float* __restrict__ bias, float* __restrict__ C) {
    constexpr int TN = FOUT / 16;       // 4 (FOUT=64) or 8 (FOUT=128)
    extern __shared__ __align__(16) float sfs[];
    float* sA = sfs;                    // [128][65]
    float* sW = sfs + FS_AROWS * FS_ASTR;  // [64][FOUT]
    const int tid = threadIdx.x;
    const int bm = blockIdx.x * FS_AROWS;

    // stage W (float4, coalesced)
    #pragma unroll
    for (int i = tid; i < 64 * FOUT / 4; i += 256)
        *(float4*)(sW + i * 4) = *(const float4*)(W + i * 4);

    // gather: 2 threads per row, 32 features (8 float4) each
    {
        int r = tid >> 1;
        int half = tid & 1;
        int gi = bm + r;
        float4 a8[8];
        if (gi < NN) {
            int base = gi * 16 + half * 8;
            float d = dis[gi];
            float s = d * d;
            #pragma unroll
            for (int j = 0; j < 8; j++) {
                float4 v = h[base + j];
                a8[j].x = s * v.x; a8[j].y = s * v.y;
                a8[j].z = s * v.z; a8[j].w = s * v.w;
            }
            int p0 = off[gi], p1 = off[gi + 1];
            for (int p = p0; p < p1; p++) {
                int sn = src[p];
                float w = enrm[p];
                int sb = sn * 16 + half * 8;
                #pragma unroll
                for (int j = 0; j < 8; j++) {
                    float4 u = h[sb + j];
                    a8[j].x += w * u.x; a8[j].y += w * u.y;
                    a8[j].z += w * u.z; a8[j].w += w * u.w;
                }
            }
        } else {
            #pragma unroll
            for (int j = 0; j < 8; j++) a8[j] = make_float4(0.f, 0.f, 0.f, 0.f);
        }
        float* dst = sA + r * FS_ASTR + half * 32;
        #pragma unroll
        for (int j = 0; j < 8; j++) {
            dst[j * 4 + 0] = a8[j].x; dst[j * 4 + 1] = a8[j].y;
            dst[j * 4 + 2] = a8[j].z; dst[j * 4 + 3] = a8[j].w;
        }
    }
    __syncthreads();

    // GEMM: C[128][FOUT] = sA @ sW
    const int tx = tid & 15;
    const int ty = tid >> 4;
    float acc[8][TN];
    #pragma unroll
    for (int m = 0; m < 8; m++)
        #pragma unroll
        for (int n = 0; n < TN; n++) acc[m][n] = 0.f;
    #pragma unroll 8
    for (int k = 0; k < 64; k++) {
        float ra[8];
        #pragma unroll
        for (int m = 0; m < 8; m++) ra[m] = sA[(ty * 8 + m) * FS_ASTR + k];
        float rb[TN];
        #pragma unroll
        for (int n = 0; n < TN; n++) rb[n] = sW[k * FOUT + tx * TN + n];
        #pragma unroll
        for (int m = 0; m < 8; m++)
            #pragma unroll
            for (int n = 0; n < TN; n++)
                acc[m][n] += ra[m] * rb[n];
    }
    float bb[TN];
    #pragma unroll
    for (int n = 0; n < TN; n++) bb[n] = bias[tx * TN + n];
    #pragma unroll
    for (int m = 0; m < 8; m++) {
        int gr = bm + ty * 8 + m;
        if (gr < NN) {
            #pragma unroll
            for (int n4 = 0; n4 < TN / 4; n4++) {
                float4 o;
                o.x = fmaxf(acc[m][n4 * 4 + 0] + bb[n4 * 4 + 0], 0.f);
                o.y = fmaxf(acc[m][n4 * 4 + 1] + bb[n4 * 4 + 1], 0.f);
                o.z = fmaxf(acc[m][n4 * 4 + 2] + bb[n4 * 4 + 2], 0.f);
                o.w = fmaxf(acc[m][n4 * 4 + 3] + bb[n4 * 4 + 3], 0.f);
                *(float4*)(C + (size_t)gr * FOUT + tx * TN + n4 * 4) = o;
            }
        }
    }
}

// ================= combined weight split (W4+W5+W6 in one launch) =================
__global__ void k_wsplit_all(const float* __restrict__ W4, const float* __restrict__ W5,
                             const float* __restrict__ W6, __half* __restrict__ Wh,
                             __half* __restrict__ Wl) {
    int idx = blockIdx.x * blockDim.x + threadIdx.x;
    if (idx >= WTOT) return;
    const float* W; int K, N, li;
    if (idx < WOFF5)      { W = W4; K = 128;  N = 1024; li = idx; }
    else if (idx < WOFF6) { W = W5; K = 1024; N = 512;  li = idx - WOFF5; }
    else                  { W = W6; K = 512;  N = 256;  li = idx - WOFF6; }
    int n = li / K;
    int k = li - n * K;
    float v = W[(size_t)k * N + n];
    __half h = __float2half(v);
    Wh[idx] = h;
    Wl[idx] = __float2half(v - __half2float(h));
}

// ================= fused-product mma.sync split-fp16 GEMM =================
// C = AhWh + AlWh + AhWl (single K sweep).
// CTA tile 128x256, BK=32, 16 warps (2m x 8n), warp tile 64x32, 3-stage pipeline.
#define MG_RSTR  80
#define MG_AT    10240
#define MG_BT    20480
#define MG_ST4   61440
#define MG_SMEM  (3 * MG_ST4)

__device__ __forceinline__ void mg_load4(
    const __half* __restrict__ Ah_, const __half* __restrict__ Al_,
    const __half* __restrict__ Bh_, const __half* __restrict__ Bl_,
    int M, int K, int bm, int bn, int koff, uint32_t st, int tid) {
    {
        int r = tid >> 2, ch = tid & 3;
        int gr = bm + r;
        if (gr >= M) gr = M - 1;
        CP_ASYNC16(st + r * MG_RSTR + ch * 16,
                   (const void*)(Ah_ + (size_t)gr * K + koff + ch * 8));
        CP_ASYNC16(st + MG_AT + r * MG_RSTR + ch * 16,
                   (const void*)(Al_ + (size_t)gr * K + koff + ch * 8));
    }
    #pragma unroll
    for (int i = 0; i < 2; i++) {
        int idx = tid + i * 512;
        int r = idx >> 2, ch = idx & 3;
        CP_ASYNC16(st + 2 * MG_AT + r * MG_RSTR + ch * 16,
                   (const void*)(Bh_ + (size_t)(bn + r) * K + koff + ch * 8));
        CP_ASYNC16(st + 2 * MG_AT + MG_BT + r * MG_RSTR + ch * 16,
                   (const void*)(Bl_ + (size_t)(bn + r) * K + koff + ch * 8));
    }
    CP_COMMIT();
}

template <bool BIAS_RELU, bool SPLIT>
__global__ void __launch_bounds__(512, 1) k_mma_gemm(
    const __half* __restrict__ Ahi, const __half* __restrict__ Alo,
    const __half* __restrict__ Bhi, const __half* __restrict__ Blo,
    const float* __restrict__ bias, float* __restrict__ Cf,
    __half2* __restrict__ Chi, __half2* __restrict__ Clo,
    int M, int N, int K) {
    extern __shared__ __align__(16) char smx[];
    const uint32_t sbase = smem_to_u32(smx);
    const int tid = threadIdx.x;
    const int lane = tid & 31;
    const int wid = tid >> 5;
    const int wm = (wid & 1) * 64;
    const int wn = (wid >> 1) * 32;
    const int bm = blockIdx.y * 128;
    const int bn = blockIdx.x * 256;

    const int CK = K / 32;

    float acc[4][4][4];
    #pragma unroll
    for (int i = 0; i < 4; i++)
        #pragma unroll
        for (int j = 0; j < 4; j++)
            #pragma unroll
            for (int q = 0; q < 4; q++) acc[i][j][q] = 0.f;

    mg_load4(Ahi, Alo, Bhi, Blo, M, K, bm, bn, 0, sbase, tid);
    if (CK > 1)
        mg_load4(Ahi, Alo, Bhi, Blo, M, K, bm, bn, 32, sbase + MG_ST4, tid);

    int sidx = 0;
    for (int c = 0; c < CK; c++) {
        if (c + 2 < CK) {
            int s2 = (sidx + 2) % 3;
            mg_load4(Ahi, Alo, Bhi, Blo, M, K, bm, bn, (c + 2) * 32,
                     sbase + s2 * MG_ST4, tid);
            CP_WAIT(2);
        } else if (c + 1 < CK) {
            CP_WAIT(1);
        } else {
            CP_WAIT(0);
        }
        __syncthreads();

        const uint32_t base = sbase + sidx * MG_ST4;
        #pragma unroll
        for (int kk = 0; kk < 32; kk += 16) {
            uint32_t ah[4][4], al[4][4];
            #pragma unroll
            for (int mi = 0; mi < 4; mi++) {
                int r = wm + mi * 16 + (lane & 15);
                int colb = (kk + ((lane >> 4) << 3)) * 2;
                LDSM_X4(ah[mi][0], ah[mi][1], ah[mi][2], ah[mi][3],
                        base + r * MG_RSTR + colb);
                LDSM_X4(al[mi][0], al[mi][1], al[mi][2], al[mi][3],
                        base + MG_AT + r * MG_RSTR + colb);
            }
            uint32_t bh[4][2], bl[4][2];
            #pragma unroll
            for (int nb = 0; nb < 2; nb++) {
                int n = wn + nb * 16 + (lane & 7) + ((lane >> 4) << 3);
                int colb = (kk + (((lane >> 3) & 1) << 3)) * 2;
                LDSM_X4(bh[2 * nb][0], bh[2 * nb][1], bh[2 * nb + 1][0], bh[2 * nb + 1][1],
                        base + 2 * MG_AT + n * MG_RSTR + colb);
                LDSM_X4(bl[2 * nb][0], bl[2 * nb][1], bl[2 * nb + 1][0], bl[2 * nb + 1][1],
                        base + 2 * MG_AT + MG_BT + n * MG_RSTR + colb);
            }
            #pragma unroll
            for (int mi = 0; mi < 4; mi++)
                #pragma unroll
                for (int nj = 0; nj < 4; nj++)
                    MMA_16816(acc[mi][nj], ah[mi], bh[nj]);
            #pragma unroll
            for (int mi = 0; mi < 4; mi++)
                #pragma unroll
                for (int nj = 0; nj < 4; nj++)
                    MMA_16816(acc[mi][nj], al[mi], bh[nj]);
            #pragma unroll
            for (int mi = 0; mi < 4; mi++)
                #pragma unroll
                for (int nj = 0; nj < 4; nj++)
                    MMA_16816(acc[mi][nj], ah[mi], bl[nj]);
        }
        __syncthreads();
        sidx = (sidx + 1) % 3;
    }

    // epilogue
    #pragma unroll
    for (int mi = 0; mi < 4; mi++) {
        int r0 = bm + wm + mi * 16 + (lane >> 2);
        #pragma unroll
        for (int nj = 0; nj < 4; nj++) {
            int cn = bn + wn + nj * 8 + (lane & 3) * 2;
            float2 v0, v1;
            v0.x = acc[mi][nj][0]; v0.y = acc[mi][nj][1];
            v1.x = acc[mi][nj][2]; v1.y = acc[mi][nj][3];
            if (BIAS_RELU) {
                float b0 = bias[cn], b1 = bias[cn + 1];
                v0.x = fmaxf(v0.x + b0, 0.f); v0.y = fmaxf(v0.y + b1, 0.f);
                v1.x = fmaxf(v1.x + b0, 0.f); v1.y = fmaxf(v1.y + b1, 0.f);
            }
            if (SPLIT) {
                #pragma unroll
                for (int rr = 0; rr < 2; rr++) {
                    int r = r0 + rr * 8;
                    if (r < M) {
                        float2 v = rr ? v1 : v0;
                        __half hx = __float2half(v.x), hy = __float2half(v.y);
                        __half lx = __float2half(v.x - __half2float(hx));
                        __half ly = __float2half(v.y - __half2float(hy));
                        size_t o = ((size_t)r * N + cn) >> 1;
                        Chi[o] = __halves2half2(hx, hy);
                        Clo[o] = __halves2half2(lx, ly);
                    }
                }
            } else {
                if (r0 < M)     *(float2*)(Cf + (size_t)r0 * N + cn) = v0;
                if (r0 + 8 < M) *(float2*)(Cf + (size_t)(r0 + 8) * N + cn) = v1;
            }
        }
    }
}

// ---------------- layer-0 GEMM (K=3, Fout=64, bias+relu) ----------------
__global__ void k_l0_gemm(const float* __restrict__ t, const float* __restrict__ W,
                          const float* __restrict__ b, float* __restrict__ y) {
    int idx = blockIdx.x * blockDim.x + threadIdx.x;
    if (idx >= NN * 64) return;
    int i = idx >> 6;
    int j = idx & 63;
    float acc = b[j];
    acc += t[i * 3 + 0] * W[0 * 64 + j];
    acc += t[i * 3 + 1] * W[1 * 64 + j];
    acc += t[i * 3 + 2] * W[2 * 64 + j];
    y[idx] = fmaxf(acc, 0.f);
}

// ---------------- layer-7 GEMM (K=256, Fout=2) with fused input relu ----
__global__ void k_l7_gemm(const float* __restrict__ x, const float* __restrict__ W,
                          float* __restrict__ h) {
    int gwarp = (blockIdx.x * blockDim.x + threadIdx.x) >> 5;
    int lane = threadIdx.x & 31;
    if (gwarp >= NN) return;
    const float4* xr = (const float4*)(x + (size_t)gwarp * 256);
    float a0 = 0.f, a1 = 0.f;
    #pragma unroll
    for (int it = 0; it < 2; it++) {
        int c4 = lane + it * 32;
        float4 v = xr[c4];
        v.x = fmaxf(v.x, 0.f); v.y = fmaxf(v.y, 0.f);
        v.z = fmaxf(v.z, 0.f); v.w = fmaxf(v.w, 0.f);
        int k = c4 * 4;
        a0 += v.x * W[(k + 0) * 2 + 0] + v.y * W[(k + 1) * 2 + 0]
            + v.z * W[(k + 2) * 2 + 0] + v.w * W[(k + 3) * 2 + 0];
        a1 += v.x * W[(k + 0) * 2 + 1] + v.y * W[(k + 1) * 2 + 1]
            + v.z * W[(k + 2) * 2 + 1] + v.w * W[(k + 3) * 2 + 1];
    }
    #pragma unroll
    for (int off = 16; off > 0; off >>= 1) {
        a0 += __shfl_down_sync(0xFFFFFFFFu, a0, off);
        a1 += __shfl_down_sync(0xFFFFFFFFu, a1, off);
    }
    if (lane == 0) {
        h[gwarp * 2 + 0] = a0;
        h[gwarp * 2 + 1] = a1;
    }
}

// ================= host orchestration =================
extern "C" void kernel_launch(void* const* d_in, const int* in_sizes, int n_in,
                              void* d_out, int out_size) {
    const float* x = (const float*)d_in[0];
    const int* ei  = (const int*)d_in[1];
    const int* row = ei;
    const int* col = ei + EE;
    const float* W[8];
    const float* b[8];
    for (int i = 0; i < 8; i++) {
        W[i] = (const float*)d_in[2 + 2 * i];
        b[i] = (const float*)d_in[3 + 2 * i];
    }
    float *bufA, *bufB, *dis, *enrm;
    __half *Ahi, *Alo, *Bhi, *Blo, *Wh, *Wl;
    int *cnt, *cur, *off, *bsum, *src;
    cudaGetSymbolAddress((void**)&bufA, g_bufA);
    cudaGetSymbolAddress((void**)&bufB, g_bufB);
    cudaGetSymbolAddress((void**)&Ahi,  g_Ahi);
    cudaGetSymbolAddress((void**)&Alo,  g_Alo);
    cudaGetSymbolAddress((void**)&Bhi,  g_Bhi);
    cudaGetSymbolAddress((void**)&Blo,  g_Blo);
    cudaGetSymbolAddress((void**)&Wh,   g_Wh);
    cudaGetSymbolAddress((void**)&Wl,   g_Wl);
    cudaGetSymbolAddress((void**)&cnt,  g_cnt);
    cudaGetSymbolAddress((void**)&cur,  g_cur);
    cudaGetSymbolAddress((void**)&off,  g_off);
    cudaGetSymbolAddress((void**)&bsum, g_bsum);
    cudaGetSymbolAddress((void**)&dis,  g_dis);
    cudaGetSymbolAddress((void**)&src,  g_src);
    cudaGetSymbolAddress((void**)&enrm, g_enrm);
    float* out = (float*)d_out;

    cudaFuncSetAttribute(k_mma_gemm<true, true>,
                         cudaFuncAttributeMaxDynamicSharedMemorySize, MG_SMEM);
    cudaFuncSetAttribute(k_mma_gemm<false, false>,
                         cudaFuncAttributeMaxDynamicSharedMemorySize, MG_SMEM);
    const int fs64_smem  = FS_ABYTES + 64 * 64 * 4;    // 49664 B
    const int fs128_smem = FS_ABYTES + 64 * 128 * 4;   // 66048 B
    cudaFuncSetAttribute(k_fused_small<64>,
                         cudaFuncAttributeMaxDynamicSharedMemorySize, fs64_smem);
    cudaFuncSetAttribute(k_fused_small<128>,
                         cudaFuncAttributeMaxDynamicSharedMemorySize, fs128_smem);

    // ---- CSR build + all weight splits ----
    k_zero2<<<(NN + 255) / 256, 256>>>(cnt, cur);
    k_cnt<<<(EE + 255) / 256, 256>>>(col, cnt);
    k_scan1<<<SCAN_NB, SCAN_BS>>>(cnt, off, bsum);
    k_scan2<<<1, 128>>>(bsum);
    k_scan3<<<(NN + 255) / 256, 256>>>(off, bsum, cnt, dis);
    k_fill<<<(EE + 255) / 256, 256>>>(row, col, dis, off, cur, src, enrm);
    k_wsplit_all<<<(WTOT + 255) / 256, 256>>>(W[4], W[5], W[6], Wh, Wl);

    // ---- L0: 3 -> 64 ----
    k_gather1<3, false><<<(NN * 3 + 255) / 256, 256>>>(x, off, src, enrm, dis, nullptr, bufA);
    k_l0_gemm<<<(NN * 64 + 255) / 256, 256>>>(bufA, W[0], b[0], bufB);

    // ---- L1-L3: fused gather+GEMM (fp32, exact) ----
    k_fused_small<64><<<(NN + 127) / 128, 256, fs64_smem>>>(
        (const float4*)bufB, off, src, enrm, dis, W[1], b[1], bufA);
    k_fused_small<64><<<(NN + 127) / 128, 256, fs64_smem>>>(
        (const float4*)bufA, off, src, enrm, dis, W[2], b[2], bufB);
    k_fused_small<128><<<(NN + 127) / 128, 256, fs128_smem>>>(
        (const float4*)bufB, off, src, enrm, dis, W[3], b[3], bufA);

    // ---- L4: 128 -> 1024 (gather->split, mma with bias+relu, split output) ----
    k_gather4<128, false, false, true><<<(NN * 32 + 255) / 256, 256>>>(
        (const float4*)bufA, off, src, enrm, dis, nullptr, nullptr, (__half2*)Ahi, (__half2*)Alo);
    k_mma_gemm<true, true><<<dim3(4, (NN + 127) / 128), 512, MG_SMEM>>>(
        Ahi, Alo, Wh + WOFF4, Wl + WOFF4, b[4], nullptr,
        (__half2*)Bhi, (__half2*)Blo, NN, 1024, 128);

    // ---- L5: 1024 -> 512 (mma fp32 out; gather fuses bias+relu+split) ----
    k_mma_gemm<false, false><<<dim3(2, (NN + 127) / 128), 512, MG_SMEM>>>(
        Bhi, Blo, Wh + WOFF5, Wl + WOFF5, nullptr, bufA, nullptr, nullptr, NN, 512, 1024);
    k_gather4<512, true, true, true><<<(NN * 128 + 255) / 256, 256>>>(
        (const float4*)bufA, off, src, enrm, dis, b[5], nullptr, (__half2*)Ahi, (__half2*)Alo);

    // ---- L6: 512 -> 256 (mma fp32 out; gather fuses bias; relu in L7 load) ----
    k_mma_gemm<false, false><<<dim3(1, (NN + 127) / 128), 512, MG_SMEM>>>(
        Ahi, Alo, Wh + WOFF6, Wl + WOFF6, nullptr, bufB, nullptr, nullptr, NN, 256, 512);
    k_gather4<256, true, false, false><<<(NN * 64 + 255) / 256, 256>>>(
        (const float4*)bufB, off, src, enrm, dis, b[6], (float4*)bufA, nullptr, nullptr);

    // ---- L7: 256 -> 2 (relu fused into gemm load; gather fuses bias, writes d_out) ----
    k_l7_gemm<<<(NN * 32 + 255) / 256, 256>>>(bufA, W[7], bufB);
    k_gather1<2, true><<<(NN * 2 + 255) / 256, 256>>>(bufB, off, src, enrm, dis, b[7], out);
}

// round 14
// speedup vs baseline: 1.0267x; 1.0267x over previous
#include <cuda_runtime.h>
#include <cuda_fp16.h>
#include <cstdint>
#include <math.h>

#define NN 50000
#define EE 200000
#define SCAN_BS 512
#define SCAN_NB 98          // ceil(NN/512)

// weight-split packing offsets (elements) inside g_Wh / g_Wl
#define WOFF4 0
#define WOFF5 131072        // 128*1024
#define WOFF6 655360        // +1024*512
#define WTOT  786432        // +512*256

// ---------------- scratch (static device globals; allocation-free) ----------------
__device__ float g_bufA[(size_t)NN * 1024];
__device__ float g_bufB[(size_t)NN * 1024];
__device__ __half g_Ahi[(size_t)NN * 1024];
__device__ __half g_Alo[(size_t)NN * 1024];
__device__ __half g_Bhi[(size_t)NN * 1024];
__device__ __half g_Blo[(size_t)NN * 1024];
__device__ __half g_Wh[WTOT];
__device__ __half g_Wl[WTOT];
__device__ int   g_cnt[NN];
__device__ int   g_cur[NN];
__device__ int   g_off[NN + 1];
__device__ int   g_bsum[SCAN_NB];
__device__ float g_dis[NN];
__device__ int   g_src[EE];
__device__ float g_enrm[EE];

// ================= PTX helpers (arch-generic: sm_80+) =================
__device__ __forceinline__ uint32_t smem_to_u32(const void* p) {
    uint32_t a;
    asm("{ .reg .u64 t; cvta.to.shared.u64 t, %1; cvt.u32.u64 %0, t; }" : "=r"(a) : "l"(p));
    return a;
}
#define CP_ASYNC16(dst, src) \
    asm volatile("cp.async.cg.shared.global [%0], [%1], 16;" :: "r"(dst), "l"(src))
#define CP_COMMIT() asm volatile("cp.async.commit_group;" ::: "memory")
#define CP_WAIT(n)  asm volatile("cp.async.wait_group %0;" :: "n"(n) : "memory")
#define LDSM_X4(r0, r1, r2, r3, addr) \
    asm volatile("ldmatrix.sync.aligned.m8n8.x4.shared.b16 {%0,%1,%2,%3}, [%4];" \
        : "=r"(r0), "=r"(r1), "=r"(r2), "=r"(r3) : "r"(addr))
#define MMA_16816(c, a, b) \
    asm volatile("mma.sync.aligned.m16n8k16.row.col.f32.f16.f16.f32 " \
        "{%0,%1,%2,%3}, {%4,%5,%6,%7}, {%8,%9}, {%0,%1,%2,%3};" \
        : "+f"((c)[0]), "+f"((c)[1]), "+f"((c)[2]), "+f"((c)[3]) \
        : "r"((a)[0]), "r"((a)[1]), "r"((a)[2]), "r"((a)[3]), "r"((b)[0]), "r"((b)[1]))

// ================= CSR build =================
__global__ void k_cnt(const int* __restrict__ col, int* __restrict__ cnt) {
    int e = blockIdx.x * blockDim.x + threadIdx.x;
    if (e < EE) atomicAdd(&cnt[col[e]], 1);
}
__global__ void k_scan1(const int* __restrict__ cnt, int* __restrict__ off,
                        int* __restrict__ bsum) {
    __shared__ int sh[SCAN_BS];
    int tid = threadIdx.x;
    int i = blockIdx.x * SCAN_BS + tid;
    int v = (i < NN) ? cnt[i] : 0;
    sh[tid] = v;
    __syncthreads();
    #pragma unroll
    for (int d = 1; d < SCAN_BS; d <<= 1) {
        int t = (tid >= d) ? sh[tid - d] : 0;
        __syncthreads();
        sh[tid] += t;
        __syncthreads();
    }
    if (i < NN) off[i] = sh[tid] - v;          // exclusive
    if (tid == SCAN_BS - 1) bsum[blockIdx.x] = sh[tid];
}
__global__ void k_scan2(int* __restrict__ bsum) {
    __shared__ int sh[128];
    int tid = threadIdx.x;
    int v = (tid < SCAN_NB) ? bsum[tid] : 0;
    sh[tid] = v;
    __syncthreads();
    #pragma unroll
    for (int d = 1; d < 128; d <<= 1) {
        int t = (tid >= d) ? sh[tid - d] : 0;
        __syncthreads();
        sh[tid] += t;
        __syncthreads();
    }
    if (tid < SCAN_NB) bsum[tid] = sh[tid] - v;  // exclusive
}
// also computes dis = rsqrt(deg)
__global__ void k_scan3(int* __restrict__ off, const int* __restrict__ bsum,
                        const int* __restrict__ cnt, float* __restrict__ dis) {
    int i = blockIdx.x * blockDim.x + threadIdx.x;
    if (i < NN) {
        off[i] += bsum[i / SCAN_BS];
        dis[i] = rsqrtf((float)(cnt[i] + 1));
    }
    if (i == 0) off[NN] = EE;
}
__global__ void k_fill(const int* __restrict__ row, const int* __restrict__ col,
                       const float* __restrict__ dis, const int* __restrict__ off,
                       int* __restrict__ cur, int* __restrict__ src,
                       float* __restrict__ enrm) {
    int e = blockIdx.x * blockDim.x + threadIdx.x;
    if (e >= EE) return;
    int r = row[e], c = col[e];
    int pos = off[c] + atomicAdd(&cur[c], 1);
    src[pos] = r;
    enrm[pos] = dis[r] * dis[c];
}

// ================= fused CSR gather aggregation =================
template <int F, bool BIAS, bool RELU, bool SPLIT>
__global__ void __launch_bounds__(256) k_gather4(
    const float4* __restrict__ h, const int* __restrict__ off,
    const int* __restrict__ src, const float* __restrict__ enrm,
    const float* __restrict__ dis, const float* __restrict__ bias,
    float4* __restrict__ outf, __half2* __restrict__ ohi, __half2* __restrict__ olo) {
    constexpr int FV = F / 4;
    int idx = blockIdx.x * blockDim.x + threadIdx.x;
    if (idx >= NN * FV) return;
    int i = idx / FV;
    int f4 = idx - i * FV;
    float d = dis[i];
    float s = d * d;
    float4 v = h[(size_t)i * FV + f4];
    float4 acc;
    acc.x = s * v.x; acc.y = s * v.y; acc.z = s * v.z; acc.w = s * v.w;
    int p0 = off[i], p1 = off[i + 1];
    for (int p = p0; p < p1; p++) {
        int sn = src[p];
        float w = enrm[p];
        float4 u = h[(size_t)sn * FV + f4];
        acc.x += w * u.x; acc.y += w * u.y; acc.z += w * u.z; acc.w += w * u.w;
    }
    if (BIAS) {
        const float4 bv = *(const float4*)(bias + f4 * 4);
        acc.x += bv.x; acc.y += bv.y; acc.z += bv.z; acc.w += bv.w;
    }
    if (RELU) {
        acc.x = fmaxf(acc.x, 0.f); acc.y = fmaxf(acc.y, 0.f);
        acc.z = fmaxf(acc.z, 0.f); acc.w = fmaxf(acc.w, 0.f);
    }
    if (SPLIT) {
        __half hx = __float2half(acc.x), hy = __float2half(acc.y);
        __half hz = __float2half(acc.z), hw = __float2half(acc.w);
        __half lx = __float2half(acc.x - __half2float(hx));
        __half ly = __float2half(acc.y - __half2float(hy));
        __half lz = __float2half(acc.z - __half2float(hz));
        __half lw = __float2half(acc.w - __half2float(hw));
        ohi[(size_t)idx * 2 + 0] = __halves2half2(hx, hy);
        ohi[(size_t)idx * 2 + 1] = __halves2half2(hz, hw);
        olo[(size_t)idx * 2 + 0] = __halves2half2(lx, ly);
        olo[(size_t)idx * 2 + 1] = __halves2half2(lz, lw);
    } else {
        outf[idx] = acc;
    }
}

// scalar variant for F=2 (final layer)
template <int F, bool BIAS>
__global__ void k_gather1(const float* __restrict__ h, const int* __restrict__ off,
                          const int* __restrict__ src, const float* __restrict__ enrm,
                          const float* __restrict__ dis, const float* __restrict__ bias,
                          float* __restrict__ outf) {
    int idx = blockIdx.x * blockDim.x + threadIdx.x;
    if (idx >= NN * F) return;
    int i = idx / F;
    int f = idx - i * F;
    float d = dis[i];
    float acc = d * d * h[(size_t)i * F + f];
    int p0 = off[i], p1 = off[i + 1];
    for (int p = p0; p < p1; p++)
        acc += enrm[p] * h[(size_t)src[p] * F + f];
    if (BIAS) acc += bias[f];
    outf[idx] = acc;
}

// ================= fused L0: gather@3 + GEMM 3->64 + bias + relu =================
// Safe fusion: gathered row is only 3 floats (3 threads/row, trivial loop).
__global__ void __launch_bounds__(256) k_l0_fused(
    const float* __restrict__ x, const int* __restrict__ off,
    const int* __restrict__ src, const float* __restrict__ enrm,
    const float* __restrict__ dis, const float* __restrict__ W,
    const float* __restrict__ b, float* __restrict__ y) {
    __shared__ float sX[64][3];
    __shared__ float sW[3][64];
    __shared__ float sB[64];
    int tid = threadIdx.x;
    int bn0 = blockIdx.x * 64;
    if (tid < 192) sW[tid / 64][tid % 64] = W[tid];      // W is [3,64] row-major
    if (tid >= 192) sB[tid - 192] = b[tid - 192];
    if (tid < 192) {
        int n = tid / 3, f = tid - n * 3;
        int gi = bn0 + n;
        float acc = 0.f;
        if (gi < NN) {
            float d = dis[gi];
            acc = d * d * x[gi * 3 + f];
            int p0 = off[gi], p1 = off[gi + 1];
            for (int p = p0; p < p1; p++)
                acc += enrm[p] * x[src[p] * 3 + f];
        }
        sX[n][f] = acc;
    }
    __syncthreads();
    #pragma unroll
    for (int k = 0; k < 16; k++) {
        int o = tid + k * 256;
        int n = o >> 6, j = o & 63;
        int gi = bn0 + n;
        if (gi < NN) {
            float acc = sB[j] + sX[n][0] * sW[0][j] + sX[n][1] * sW[1][j]
                      + sX[n][2] * sW[2][j];
            y[(size_t)gi * 64 + j] = fmaxf(acc, 0.f);
        }
    }
}

// ================= combined weight split (W4+W5+W6 in one launch) =================
__global__ void k_wsplit_all(const float* __restrict__ W4, const float* __restrict__ W5,
                             const float* __restrict__ W6, __half* __restrict__ Wh,
                             __half* __restrict__ Wl) {
    int idx = blockIdx.x * blockDim.x + threadIdx.x;
    if (idx >= WTOT) return;
    const float* W; int K, N, li;
    if (idx < WOFF5)      { W = W4; K = 128;  N = 1024; li = idx; }
    else if (idx < WOFF6) { W = W5; K = 1024; N = 512;  li = idx - WOFF5; }
    else                  { W = W6; K = 512;  N = 256;  li = idx - WOFF6; }
    int n = li / K;
    int k = li - n * K;
    float v = W[(size_t)k * N + n];
    __half h = __float2half(v);
    Wh[idx] = h;
    Wl[idx] = __float2half(v - __half2float(h));
}

// ================= fused-product mma.sync split-fp16 GEMM =================
// C = AhWh + AlWh + AhWl (single K sweep).
// CTA tile 128x256, BK=32, 16 warps (2m x 8n), warp tile 64x32, 3-stage pipeline.
#define MG_RSTR  80
#define MG_AT    10240
#define MG_BT    20480
#define MG_ST4   61440
#define MG_SMEM  (3 * MG_ST4)

__device__ __forceinline__ void mg_load4(
    const __half* __restrict__ Ah_, const __half* __restrict__ Al_,
    const __half* __restrict__ Bh_, const __half* __restrict__ Bl_,
    int M, int K, int bm, int bn, int koff, uint32_t st, int tid) {
    {
        int r = tid >> 2, ch = tid & 3;
        int gr = bm + r;
        if (gr >= M) gr = M - 1;
        CP_ASYNC16(st + r * MG_RSTR + ch * 16,
                   (const void*)(Ah_ + (size_t)gr * K + koff + ch * 8));
        CP_ASYNC16(st + MG_AT + r * MG_RSTR + ch * 16,
                   (const void*)(Al_ + (size_t)gr * K + koff + ch * 8));
    }
    #pragma unroll
    for (int i = 0; i < 2; i++) {
        int idx = tid + i * 512;
        int r = idx >> 2, ch = idx & 3;
        CP_ASYNC16(st + 2 * MG_AT + r * MG_RSTR + ch * 16,
                   (const void*)(Bh_ + (size_t)(bn + r) * K + koff + ch * 8));
        CP_ASYNC16(st + 2 * MG_AT + MG_BT + r * MG_RSTR + ch * 16,
                   (const void*)(Bl_ + (size_t)(bn + r) * K + koff + ch * 8));
    }
    CP_COMMIT();
}

template <bool BIAS_RELU, bool SPLIT>
__global__ void __launch_bounds__(512, 1) k_mma_gemm(
    const __half* __restrict__ Ahi, const __half* __restrict__ Alo,
    const __half* __restrict__ Bhi, const __half* __restrict__ Blo,
    const float* __restrict__ bias, float* __restrict__ Cf,
    __half2* __restrict__ Chi, __half2* __restrict__ Clo,
    int M, int N, int K) {
    extern __shared__ __align__(16) char smx[];
    const uint32_t sbase = smem_to_u32(smx);
    const int tid = threadIdx.x;
    const int lane = tid & 31;
    const int wid = tid >> 5;
    const int wm = (wid & 1) * 64;
    const int wn = (wid >> 1) * 32;
    const int bm = blockIdx.y * 128;
    const int bn = blockIdx.x * 256;

    const int CK = K / 32;

    float acc[4][4][4];
    #pragma unroll
    for (int i = 0; i < 4; i++)
        #pragma unroll
        for (int j = 0; j < 4; j++)
            #pragma unroll
            for (int q = 0; q < 4; q++) acc[i][j][q] = 0.f;

    mg_load4(Ahi, Alo, Bhi, Blo, M, K, bm, bn, 0, sbase, tid);
    if (CK > 1)
        mg_load4(Ahi, Alo, Bhi, Blo, M, K, bm, bn, 32, sbase + MG_ST4, tid);

    int sidx = 0;
    for (int c = 0; c < CK; c++) {
        if (c + 2 < CK) {
            int s2 = (sidx + 2) % 3;
            mg_load4(Ahi, Alo, Bhi, Blo, M, K, bm, bn, (c + 2) * 32,
                     sbase + s2 * MG_ST4, tid);
            CP_WAIT(2);
        } else if (c + 1 < CK) {
            CP_WAIT(1);
        } else {
            CP_WAIT(0);
        }
        __syncthreads();

        const uint32_t base = sbase + sidx * MG_ST4;
        #pragma unroll
        for (int kk = 0; kk < 32; kk += 16) {
            uint32_t ah[4][4], al[4][4];
            #pragma unroll
            for (int mi = 0; mi < 4; mi++) {
                int r = wm + mi * 16 + (lane & 15);
                int colb = (kk + ((lane >> 4) << 3)) * 2;
                LDSM_X4(ah[mi][0], ah[mi][1], ah[mi][2], ah[mi][3],
                        base + r * MG_RSTR + colb);
                LDSM_X4(al[mi][0], al[mi][1], al[mi][2], al[mi][3],
                        base + MG_AT + r * MG_RSTR + colb);
            }
            uint32_t bh[4][2], bl[4][2];
            #pragma unroll
            for (int nb = 0; nb < 2; nb++) {
                int n = wn + nb * 16 + (lane & 7) + ((lane >> 4) << 3);
                int colb = (kk + (((lane >> 3) & 1) << 3)) * 2;
                LDSM_X4(bh[2 * nb][0], bh[2 * nb][1], bh[2 * nb + 1][0], bh[2 * nb + 1][1],
                        base + 2 * MG_AT + n * MG_RSTR + colb);
                LDSM_X4(bl[2 * nb][0], bl[2 * nb][1], bl[2 * nb + 1][0], bl[2 * nb + 1][1],
                        base + 2 * MG_AT + MG_BT + n * MG_RSTR + colb);
            }
            #pragma unroll
            for (int mi = 0; mi < 4; mi++)
                #pragma unroll
                for (int nj = 0; nj < 4; nj++)
                    MMA_16816(acc[mi][nj], ah[mi], bh[nj]);
            #pragma unroll
            for (int mi = 0; mi < 4; mi++)
                #pragma unroll
                for (int nj = 0; nj < 4; nj++)
                    MMA_16816(acc[mi][nj], al[mi], bh[nj]);
            #pragma unroll
            for (int mi = 0; mi < 4; mi++)
                #pragma unroll
                for (int nj = 0; nj < 4; nj++)
                    MMA_16816(acc[mi][nj], ah[mi], bl[nj]);
        }
        __syncthreads();
        sidx = (sidx + 1) % 3;
    }

    // epilogue
    #pragma unroll
    for (int mi = 0; mi < 4; mi++) {
        int r0 = bm + wm + mi * 16 + (lane >> 2);
        #pragma unroll
        for (int nj = 0; nj < 4; nj++) {
            int cn = bn + wn + nj * 8 + (lane & 3) * 2;
            float2 v0, v1;
            v0.x = acc[mi][nj][0]; v0.y = acc[mi][nj][1];
            v1.x = acc[mi][nj][2]; v1.y = acc[mi][nj][3];
            if (BIAS_RELU) {
                float b0 = bias[cn], b1 = bias[cn + 1];
                v0.x = fmaxf(v0.x + b0, 0.f); v0.y = fmaxf(v0.y + b1, 0.f);
                v1.x = fmaxf(v1.x + b0, 0.f); v1.y = fmaxf(v1.y + b1, 0.f);
            }
            if (SPLIT) {
                #pragma unroll
                for (int rr = 0; rr < 2; rr++) {
                    int r = r0 + rr * 8;
                    if (r < M) {
                        float2 v = rr ? v1 : v0;
                        __half hx = __float2half(v.x), hy = __float2half(v.y);
                        __half lx = __float2half(v.x - __half2float(hx));
                        __half ly = __float2half(v.y - __half2float(hy));
                        size_t o = ((size_t)r * N + cn) >> 1;
                        Chi[o] = __halves2half2(hx, hy);
                        Clo[o] = __halves2half2(lx, ly);
                    }
                }
            } else {
                if (r0 < M)     *(float2*)(Cf + (size_t)r0 * N + cn) = v0;
                if (r0 + 8 < M) *(float2*)(Cf + (size_t)(r0 + 8) * N + cn) = v1;
            }
        }
    }
}

// ================= SIMT GEMM (small layers L1-L3) =================
template <bool RELU, bool BIAS>
__global__ void __launch_bounds__(256) k_gemm(
    const float* __restrict__ A, const float* __restrict__ B,
    const float* __restrict__ bias, float* __restrict__ C,
    int M, int N, int K) {
    constexpr int BMx = 128, BNx = 64, BK = 16, TM = 8, TN = 4;
    constexpr int AST = BMx + 4;
    __shared__ float As[BK * AST];
    __shared__ float Bs[BK * BNx];
    const int tid = threadIdx.x;
    const int bm = blockIdx.y * BMx;
    const int bn = blockIdx.x * BNx;
    const int tx = tid & 15;
    const int ty = tid >> 4;
    const int ar = tid >> 2;
    const int ac = (tid & 3) * 4;
    const int br = tid >> 4;
    const int bc = (tid & 15) * 4;
    float acc[TM][TN] = {};
    for (int kt = 0; kt < K; kt += BK) {
        #pragma unroll
        for (int i = 0; i < 2; i++) {
            int r = ar + i * 64;
            int gr = bm + r;
            float4 v = make_float4(0.f, 0.f, 0.f, 0.f);
            if (gr < M) v = *(const float4*)(A + (size_t)gr * K + kt + ac);
            As[(ac + 0) * AST + r] = v.x;
            As[(ac + 1) * AST + r] = v.y;
            As[(ac + 2) * AST + r] = v.z;
            As[(ac + 3) * AST + r] = v.w;
        }
        {
            float4 v = *(const float4*)(B + (size_t)(kt + br) * N + bn + bc);
            *(float4*)(Bs + br * BNx + bc) = v;
        }
        __syncthreads();
        #pragma unroll
        for (int k = 0; k < BK; k++) {
            float ra[TM], rb[TN];
            float4 a0 = *(const float4*)(As + k * AST + ty * TM);
            float4 a1 = *(const float4*)(As + k * AST + ty * TM + 4);
            ra[0] = a0.x; ra[1] = a0.y; ra[2] = a0.z; ra[3] = a0.w;
            ra[4] = a1.x; ra[5] = a1.y; ra[6] = a1.z; ra[7] = a1.w;
            float4 b0 = *(const float4*)(Bs + k * BNx + tx * TN);
            rb[0] = b0.x; rb[1] = b0.y; rb[2] = b0.z; rb[3] = b0.w;
            #pragma unroll
            for (int m = 0; m < TM; m++)
                #pragma unroll
                for (int n = 0; n < TN; n++)
                    acc[m][n] += ra[m] * rb[n];
        }
        __syncthreads();
    }
    float bv[TN] = {0.f, 0.f, 0.f, 0.f};
    if (BIAS) {
        float4 t = *(const float4*)(bias + bn + tx * TN);
        bv[0] = t.x; bv[1] = t.y; bv[2] = t.z; bv[3] = t.w;
    }
    #pragma unroll
    for (int m = 0; m < TM; m++) {
        int gr = bm + ty * TM + m;
        if (gr < M) {
            float4 o;
            o.x = acc[m][0] + bv[0];
            o.y = acc[m][1] + bv[1];
            o.z = acc[m][2] + bv[2];
            o.w = acc[m][3] + bv[3];
            if (RELU) {
                o.x = fmaxf(o.x, 0.f); o.y = fmaxf(o.y, 0.f);
                o.z = fmaxf(o.z, 0.f); o.w = fmaxf(o.w, 0.f);
            }
            *(float4*)(C + (size_t)gr * N + bn + tx * TN) = o;
        }
    }
}

// ---------------- layer-7 GEMM (K=256, Fout=2) with fused input relu ----
__global__ void k_l7_gemm(const float* __restrict__ x, const float* __restrict__ W,
                          float* __restrict__ h) {
    int gwarp = (blockIdx.x * blockDim.x + threadIdx.x) >> 5;
    int lane = threadIdx.x & 31;
    if (gwarp >= NN) return;
    const float4* xr = (const float4*)(x + (size_t)gwarp * 256);
    float a0 = 0.f, a1 = 0.f;
    #pragma unroll
    for (int it = 0; it < 2; it++) {
        int c4 = lane + it * 32;
        float4 v = xr[c4];
        v.x = fmaxf(v.x, 0.f); v.y = fmaxf(v.y, 0.f);
        v.z = fmaxf(v.z, 0.f); v.w = fmaxf(v.w, 0.f);
        int k = c4 * 4;
        a0 += v.x * W[(k + 0) * 2 + 0] + v.y * W[(k + 1) * 2 + 0]
            + v.z * W[(k + 2) * 2 + 0] + v.w * W[(k + 3) * 2 + 0];
        a1 += v.x * W[(k + 0) * 2 + 1] + v.y * W[(k + 1) * 2 + 1]
            + v.z * W[(k + 2) * 2 + 1] + v.w * W[(k + 3) * 2 + 1];
    }
    #pragma unroll
    for (int off = 16; off > 0; off >>= 1) {
        a0 += __shfl_down_sync(0xFFFFFFFFu, a0, off);
        a1 += __shfl_down_sync(0xFFFFFFFFu, a1, off);
    }
    if (lane == 0) {
        h[gwarp * 2 + 0] = a0;
        h[gwarp * 2 + 1] = a1;
    }
}

// ================= host orchestration =================
extern "C" void kernel_launch(void* const* d_in, const int* in_sizes, int n_in,
                              void* d_out, int out_size) {
    const float* x = (const float*)d_in[0];
    const int* ei  = (const int*)d_in[1];
    const int* row = ei;
    const int* col = ei + EE;
    const float* W[8];
    const float* b[8];
    for (int i = 0; i < 8; i++) {
        W[i] = (const float*)d_in[2 + 2 * i];
        b[i] = (const float*)d_in[3 + 2 * i];
    }
    float *bufA, *bufB, *dis, *enrm;
    __half *Ahi, *Alo, *Bhi, *Blo, *Wh, *Wl;
    int *cnt, *cur, *off, *bsum, *src;
    cudaGetSymbolAddress((void**)&bufA, g_bufA);
    cudaGetSymbolAddress((void**)&bufB, g_bufB);
    cudaGetSymbolAddress((void**)&Ahi,  g_Ahi);
    cudaGetSymbolAddress((void**)&Alo,  g_Alo);
    cudaGetSymbolAddress((void**)&Bhi,  g_Bhi);
    cudaGetSymbolAddress((void**)&Blo,  g_Blo);
    cudaGetSymbolAddress((void**)&Wh,   g_Wh);
    cudaGetSymbolAddress((void**)&Wl,   g_Wl);
    cudaGetSymbolAddress((void**)&cnt,  g_cnt);
    cudaGetSymbolAddress((void**)&cur,  g_cur);
    cudaGetSymbolAddress((void**)&off,  g_off);
    cudaGetSymbolAddress((void**)&bsum, g_bsum);
    cudaGetSymbolAddress((void**)&dis,  g_dis);
    cudaGetSymbolAddress((void**)&src,  g_src);
    cudaGetSymbolAddress((void**)&enrm, g_enrm);
    float* out = (float*)d_out;

    cudaFuncSetAttribute(k_mma_gemm<true, true>,
                         cudaFuncAttributeMaxDynamicSharedMemorySize, MG_SMEM);
    cudaFuncSetAttribute(k_mma_gemm<false, false>,
                         cudaFuncAttributeMaxDynamicSharedMemorySize, MG_SMEM);

    // ---- CSR build + all weight splits ----
    cudaMemsetAsync(cnt, 0, NN * sizeof(int), 0);
    cudaMemsetAsync(cur, 0, NN * sizeof(int), 0);
    k_cnt<<<(EE + 255) / 256, 256>>>(col, cnt);
    k_scan1<<<SCAN_NB, SCAN_BS>>>(cnt, off, bsum);
    k_scan2<<<1, 128>>>(bsum);
    k_scan3<<<(NN + 255) / 256, 256>>>(off, bsum, cnt, dis);
    k_fill<<<(EE + 255) / 256, 256>>>(row, col, dis, off, cur, src, enrm);
    k_wsplit_all<<<(WTOT + 255) / 256, 256>>>(W[4], W[5], W[6], Wh, Wl);

    // ---- L0: 3 -> 64 (fully fused) ----
    k_l0_fused<<<(NN + 63) / 64, 256>>>(x, off, src, enrm, dis, W[0], b[0], bufB);

    // ---- L1-L3 (separate gather + SIMT GEMM; proven config) ----
    k_gather4<64, false, false, false><<<(NN * 16 + 255) / 256, 256>>>(
        (const float4*)bufB, off, src, enrm, dis, nullptr, (float4*)bufA, nullptr, nullptr);
    k_gemm<true, true><<<dim3(1, (NN + 127) / 128), 256>>>(bufA, W[1], b[1], bufB, NN, 64, 64);

    k_gather4<64, false, false, false><<<(NN * 16 + 255) / 256, 256>>>(
        (const float4*)bufB, off, src, enrm, dis, nullptr, (float4*)bufA, nullptr, nullptr);
    k_gemm<true, true><<<dim3(1, (NN + 127) / 128), 256>>>(bufA, W[2], b[2], bufB, NN, 64, 64);

    k_gather4<64, false, false, false><<<(NN * 16 + 255) / 256, 256>>>(
        (const float4*)bufB, off, src, enrm, dis, nullptr, (float4*)bufA, nullptr, nullptr);
    k_gemm<true, true><<<dim3(2, (NN + 127) / 128), 256>>>(bufA, W[3], b[3], bufB, NN, 128, 64);

    // ---- L4: 128 -> 1024 (gather->split, mma with bias+relu, split output) ----
    k_gather4<128, false, false, true><<<(NN * 32 + 255) / 256, 256>>>(
        (const float4*)bufB, off, src, enrm, dis, nullptr, nullptr, (__half2*)Ahi, (__half2*)Alo);
    k_mma_gemm<true, true><<<dim3(4, (NN + 127) / 128), 512, MG_SMEM>>>(
        Ahi, Alo, Wh + WOFF4, Wl + WOFF4, b[4], nullptr,
        (__half2*)Bhi, (__half2*)Blo, NN, 1024, 128);

    // ---- L5: 1024 -> 512 (mma fp32 out; gather fuses bias+relu+split) ----
    k_mma_gemm<false, false><<<dim3(2, (NN + 127) / 128), 512, MG_SMEM>>>(
        Bhi, Blo, Wh + WOFF5, Wl + WOFF5, nullptr, bufA, nullptr, nullptr, NN, 512, 1024);
    k_gather4<512, true, true, true><<<(NN * 128 + 255) / 256, 256>>>(
        (const float4*)bufA, off, src, enrm, dis, b[5], nullptr, (__half2*)Ahi, (__half2*)Alo);

    // ---- L6: 512 -> 256 (mma fp32 out; gather fuses bias; relu in L7 load) ----
    k_mma_gemm<false, false><<<dim3(1, (NN + 127) / 128), 512, MG_SMEM>>>(
        Ahi, Alo, Wh + WOFF6, Wl + WOFF6, nullptr, bufB, nullptr, nullptr, NN, 256, 512);
    k_gather4<256, true, false, false><<<(NN * 64 + 255) / 256, 256>>>(
        (const float4*)bufB, off, src, enrm, dis, b[6], (float4*)bufA, nullptr, nullptr);

    // ---- L7: 256 -> 2 (relu fused into gemm load; gather fuses bias, writes d_out) ----
    k_l7_gemm<<<(NN * 32 + 255) / 256, 256>>>(bufA, W[7], bufB);
    k_gather1<2, true><<<(NN * 2 + 255) / 256, 256>>>(bufB, off, src, enrm, dis, b[7], out);
}

// round 15
// speedup vs baseline: 1.0504x; 1.0231x over previous
#include <cuda_runtime.h>
#include <cuda_fp16.h>
#include <cstdint>
#include <math.h>

#define NN 50000
#define EE 200000
#define SCAN_BS 512
#define SCAN_NB 98          // ceil(NN/512)

// weight-split packing offsets (elements) inside g_Wh / g_Wl
#define WOFF4 0
#define WOFF5 131072        // 128*1024
#define WOFF6 655360        // +1024*512
#define WTOT  786432        // +512*256

// ---------------- scratch (static device globals; allocation-free) ----------------
__device__ float g_bufA[(size_t)NN * 1024];
__device__ float g_bufB[(size_t)NN * 1024];
__device__ __half g_Ahi[(size_t)NN * 1024];
__device__ __half g_Alo[(size_t)NN * 1024];
__device__ __half g_Bhi[(size_t)NN * 1024];
__device__ __half g_Blo[(size_t)NN * 1024];
__device__ __half g_Wh[WTOT];
__device__ __half g_Wl[WTOT];
__device__ int   g_cnt[NN];
__device__ int   g_cur[NN];
__device__ int   g_off[NN + 1];
__device__ int   g_bsum[SCAN_NB];
__device__ float g_dis[NN];
__device__ int   g_src[EE];
__device__ float g_enrm[EE];

// ================= PTX helpers (arch-generic: sm_80+) =================
__device__ __forceinline__ uint32_t smem_to_u32(const void* p) {
    uint32_t a;
    asm("{ .reg .u64 t; cvta.to.shared.u64 t, %1; cvt.u32.u64 %0, t; }" : "=r"(a) : "l"(p));
    return a;
}
#define CP_ASYNC16(dst, src) \
    asm volatile("cp.async.cg.shared.global [%0], [%1], 16;" :: "r"(dst), "l"(src))
#define CP_COMMIT() asm volatile("cp.async.commit_group;" ::: "memory")
#define CP_WAIT(n)  asm volatile("cp.async.wait_group %0;" :: "n"(n) : "memory")
#define LDSM_X4(r0, r1, r2, r3, addr) \
    asm volatile("ldmatrix.sync.aligned.m8n8.x4.shared.b16 {%0,%1,%2,%3}, [%4];" \
        : "=r"(r0), "=r"(r1), "=r"(r2), "=r"(r3) : "r"(addr))
#define MMA_16816(c, a, b) \
    asm volatile("mma.sync.aligned.m16n8k16.row.col.f32.f16.f16.f32 " \
        "{%0,%1,%2,%3}, {%4,%5,%6,%7}, {%8,%9}, {%0,%1,%2,%3};" \
        : "+f"((c)[0]), "+f"((c)[1]), "+f"((c)[2]), "+f"((c)[3]) \
        : "r"((a)[0]), "r"((a)[1]), "r"((a)[2]), "r"((a)[3]), "r"((b)[0]), "r"((b)[1]))

// ================= CSR build =================
__global__ void k_cnt(const int* __restrict__ col, int* __restrict__ cnt) {
    int e = blockIdx.x * blockDim.x + threadIdx.x;
    if (e < EE) atomicAdd(&cnt[col[e]], 1);
}
__global__ void k_scan1(const int* __restrict__ cnt, int* __restrict__ off,
                        int* __restrict__ bsum) {
    __shared__ int sh[SCAN_BS];
    int tid = threadIdx.x;
    int i = blockIdx.x * SCAN_BS + tid;
    int v = (i < NN) ? cnt[i] : 0;
    sh[tid] = v;
    __syncthreads();
    #pragma unroll
    for (int d = 1; d < SCAN_BS; d <<= 1) {
        int t = (tid >= d) ? sh[tid - d] : 0;
        __syncthreads();
        sh[tid] += t;
        __syncthreads();
    }
    if (i < NN) off[i] = sh[tid] - v;          // exclusive
    if (tid == SCAN_BS - 1) bsum[blockIdx.x] = sh[tid];
}
__global__ void k_scan2(int* __restrict__ bsum) {
    __shared__ int sh[128];
    int tid = threadIdx.x;
    int v = (tid < SCAN_NB) ? bsum[tid] : 0;
    sh[tid] = v;
    __syncthreads();
    #pragma unroll
    for (int d = 1; d < 128; d <<= 1) {
        int t = (tid >= d) ? sh[tid - d] : 0;
        __syncthreads();
        sh[tid] += t;
        __syncthreads();
    }
    if (tid < SCAN_NB) bsum[tid] = sh[tid] - v;  // exclusive
}
// also computes dis = rsqrt(deg)
__global__ void k_scan3(int* __restrict__ off, const int* __restrict__ bsum,
                        const int* __restrict__ cnt, float* __restrict__ dis) {
    int i = blockIdx.x * blockDim.x + threadIdx.x;
    if (i < NN) {
        off[i] += bsum[i / SCAN_BS];
        dis[i] = rsqrtf((float)(cnt[i] + 1));
    }
    if (i == 0) off[NN] = EE;
}
__global__ void k_fill(const int* __restrict__ row, const int* __restrict__ col,
                       const float* __restrict__ dis, const int* __restrict__ off,
                       int* __restrict__ cur, int* __restrict__ src,
                       float* __restrict__ enrm) {
    int e = blockIdx.x * blockDim.x + threadIdx.x;
    if (e >= EE) return;
    int r = row[e], c = col[e];
    int pos = off[c] + atomicAdd(&cur[c], 1);
    src[pos] = r;
    enrm[pos] = dis[r] * dis[c];
}

// ================= fused CSR gather aggregation =================
template <int F, bool BIAS, bool RELU, bool SPLIT>
__global__ void __launch_bounds__(256) k_gather4(
    const float4* __restrict__ h, const int* __restrict__ off,
    const int* __restrict__ src, const float* __restrict__ enrm,
    const float* __restrict__ dis, const float* __restrict__ bias,
    float4* __restrict__ outf, __half2* __restrict__ ohi, __half2* __restrict__ olo) {
    constexpr int FV = F / 4;
    int idx = blockIdx.x * blockDim.x + threadIdx.x;
    if (idx >= NN * FV) return;
    int i = idx / FV;
    int f4 = idx - i * FV;
    float d = dis[i];
    float s = d * d;
    float4 v = h[(size_t)i * FV + f4];
    float4 acc;
    acc.x = s * v.x; acc.y = s * v.y; acc.z = s * v.z; acc.w = s * v.w;
    int p0 = off[i], p1 = off[i + 1];
    for (int p = p0; p < p1; p++) {
        int sn = src[p];
        float w = enrm[p];
        float4 u = h[(size_t)sn * FV + f4];
        acc.x += w * u.x; acc.y += w * u.y; acc.z += w * u.z; acc.w += w * u.w;
    }
    if (BIAS) {
        const float4 bv = *(const float4*)(bias + f4 * 4);
        acc.x += bv.x; acc.y += bv.y; acc.z += bv.z; acc.w += bv.w;
    }
    if (RELU) {
        acc.x = fmaxf(acc.x, 0.f); acc.y = fmaxf(acc.y, 0.f);
        acc.z = fmaxf(acc.z, 0.f); acc.w = fmaxf(acc.w, 0.f);
    }
    if (SPLIT) {
        __half hx = __float2half(acc.x), hy = __float2half(acc.y);
        __half hz = __float2half(acc.z), hw = __float2half(acc.w);
        __half lx = __float2half(acc.x - __half2float(hx));
        __half ly = __float2half(acc.y - __half2float(hy));
        __half lz = __float2half(acc.z - __half2float(hz));
        __half lw = __float2half(acc.w - __half2float(hw));
        ohi[(size_t)idx * 2 + 0] = __halves2half2(hx, hy);
        ohi[(size_t)idx * 2 + 1] = __halves2half2(hz, hw);
        olo[(size_t)idx * 2 + 0] = __halves2half2(lx, ly);
        olo[(size_t)idx * 2 + 1] = __halves2half2(lz, lw);
    } else {
        outf[idx] = acc;
    }
}

// scalar variant for F=2 (final layer)
template <int F, bool BIAS>
__global__ void k_gather1(const float* __restrict__ h, const int* __restrict__ off,
                          const int* __restrict__ src, const float* __restrict__ enrm,
                          const float* __restrict__ dis, const float* __restrict__ bias,
                          float* __restrict__ outf) {
    int idx = blockIdx.x * blockDim.x + threadIdx.x;
    if (idx >= NN * F) return;
    int i = idx / F;
    int f = idx - i * F;
    float d = dis[i];
    float acc = d * d * h[(size_t)i * F + f];
    int p0 = off[i], p1 = off[i + 1];
    for (int p = p0; p < p1; p++)
        acc += enrm[p] * h[(size_t)src[p] * F + f];
    if (BIAS) acc += bias[f];
    outf[idx] = acc;
}

// ================= fused L0: gather@3 + GEMM 3->64 + bias + relu =================
__global__ void __launch_bounds__(256) k_l0_fused(
    const float* __restrict__ x, const int* __restrict__ off,
    const int* __restrict__ src, const float* __restrict__ enrm,
    const float* __restrict__ dis, const float* __restrict__ W,
    const float* __restrict__ b, float* __restrict__ y) {
    __shared__ float sX[64][3];
    __shared__ float sW[3][64];
    __shared__ float sB[64];
    int tid = threadIdx.x;
    int bn0 = blockIdx.x * 64;
    if (tid < 192) sW[tid / 64][tid % 64] = W[tid];      // W is [3,64] row-major
    if (tid >= 192) sB[tid - 192] = b[tid - 192];
    if (tid < 192) {
        int n = tid / 3, f = tid - n * 3;
        int gi = bn0 + n;
        float acc = 0.f;
        if (gi < NN) {
            float d = dis[gi];
            acc = d * d * x[gi * 3 + f];
            int p0 = off[gi], p1 = off[gi + 1];
            for (int p = p0; p < p1; p++)
                acc += enrm[p] * x[src[p] * 3 + f];
        }
        sX[n][f] = acc;
    }
    __syncthreads();
    #pragma unroll
    for (int k = 0; k < 16; k++) {
        int o = tid + k * 256;
        int n = o >> 6, j = o & 63;
        int gi = bn0 + n;
        if (gi < NN) {
            float acc = sB[j] + sX[n][0] * sW[0][j] + sX[n][1] * sW[1][j]
                      + sX[n][2] * sW[2][j];
            y[(size_t)gi * 64 + j] = fmaxf(acc, 0.f);
        }
    }
}

// ================= fused L6-gather + L7-GEMM =================
// y[node, 0:2] = relu( A@(z6) + b6 )[node, 0:256] @ W7[256,2]
// 4 nodes/CTA, 64 threads/node (f4 = 0..63), warp-shuffle + smem reduce.
__global__ void __launch_bounds__(256) k_l6l7(
    const float4* __restrict__ h,       // z6 = x6@W6 (fp32, 256-wide, float4 view)
    const int* __restrict__ off, const int* __restrict__ src,
    const float* __restrict__ enrm, const float* __restrict__ dis,
    const float* __restrict__ b6, const float* __restrict__ W7,  // [256,2]
    float* __restrict__ y) {             // [NN,2]
    __shared__ float sW[512];
    __shared__ float sP[4][2][2];
    int tid = threadIdx.x;
    *(float2*)(sW + tid * 2) = *(const float2*)(W7 + tid * 2);
    __syncthreads();

    int idx = blockIdx.x * 256 + tid;
    int i = idx >> 6;          // node (grid sized so i < NN always)
    int f4 = idx & 63;
    // gather (identical math to k_gather4<256, BIAS=true>)
    float d = dis[i];
    float s = d * d;
    float4 v = h[(size_t)i * 64 + f4];
    float4 acc;
    acc.x = s * v.x; acc.y = s * v.y; acc.z = s * v.z; acc.w = s * v.w;
    int p0 = off[i], p1 = off[i + 1];
    for (int p = p0; p < p1; p++) {
        int sn = src[p];
        float w = enrm[p];
        float4 u = h[(size_t)sn * 64 + f4];
        acc.x += w * u.x; acc.y += w * u.y; acc.z += w * u.z; acc.w += w * u.w;
    }
    const float4 bv = *(const float4*)(b6 + f4 * 4);
    acc.x += bv.x; acc.y += bv.y; acc.z += bv.z; acc.w += bv.w;
    // relu + dot with W7
    float r0 = fmaxf(acc.x, 0.f), r1 = fmaxf(acc.y, 0.f);
    float r2 = fmaxf(acc.z, 0.f), r3 = fmaxf(acc.w, 0.f);
    int k0 = f4 * 4;
    float pa = r0 * sW[(k0 + 0) * 2 + 0] + r1 * sW[(k0 + 1) * 2 + 0]
             + r2 * sW[(k0 + 2) * 2 + 0] + r3 * sW[(k0 + 3) * 2 + 0];
    float pb = r0 * sW[(k0 + 0) * 2 + 1] + r1 * sW[(k0 + 1) * 2 + 1]
             + r2 * sW[(k0 + 2) * 2 + 1] + r3 * sW[(k0 + 3) * 2 + 1];
    #pragma unroll
    for (int o = 16; o > 0; o >>= 1) {
        pa += __shfl_down_sync(0xFFFFFFFFu, pa, o);
        pb += __shfl_down_sync(0xFFFFFFFFu, pb, o);
    }
    int lane = tid & 31;
    if (lane == 0) {
        int nb = tid >> 6;           // node in block (0..3)
        int wh = (tid >> 5) & 1;     // warp half
        sP[nb][wh][0] = pa;
        sP[nb][wh][1] = pb;
    }
    __syncthreads();
    if (tid < 8) {
        int n = tid >> 1, c = tid & 1;
        int gi = blockIdx.x * 4 + n;
        y[gi * 2 + c] = sP[n][0][c] + sP[n][1][c];
    }
}

// ================= combined weight split (W4+W5+W6 in one launch) =================
__global__ void k_wsplit_all(const float* __restrict__ W4, const float* __restrict__ W5,
                             const float* __restrict__ W6, __half* __restrict__ Wh,
                             __half* __restrict__ Wl) {
    int idx = blockIdx.x * blockDim.x + threadIdx.x;
    if (idx >= WTOT) return;
    const float* W; int K, N, li;
    if (idx < WOFF5)      { W = W4; K = 128;  N = 1024; li = idx; }
    else if (idx < WOFF6) { W = W5; K = 1024; N = 512;  li = idx - WOFF5; }
    else                  { W = W6; K = 512;  N = 256;  li = idx - WOFF6; }
    int n = li / K;
    int k = li - n * K;
    float v = W[(size_t)k * N + n];
    __half h = __float2half(v);
    Wh[idx] = h;
    Wl[idx] = __float2half(v - __half2float(h));
}

// ================= fused-product mma.sync split-fp16 GEMM =================
// C = AhWh + AlWh + AhWl (single K sweep).
// CTA tile 128x256, BK=32, 16 warps (2m x 8n), warp tile 64x32, 3-stage pipeline.
#define MG_RSTR  80
#define MG_AT    10240
#define MG_BT    20480
#define MG_ST4   61440
#define MG_SMEM  (3 * MG_ST4)

__device__ __forceinline__ void mg_load4(
    const __half* __restrict__ Ah_, const __half* __restrict__ Al_,
    const __half* __restrict__ Bh_, const __half* __restrict__ Bl_,
    int M, int K, int bm, int bn, int koff, uint32_t st, int tid) {
    {
        int r = tid >> 2, ch = tid & 3;
        int gr = bm + r;
        if (gr >= M) gr = M - 1;
        CP_ASYNC16(st + r * MG_RSTR + ch * 16,
                   (const void*)(Ah_ + (size_t)gr * K + koff + ch * 8));
        CP_ASYNC16(st + MG_AT + r * MG_RSTR + ch * 16,
                   (const void*)(Al_ + (size_t)gr * K + koff + ch * 8));
    }
    #pragma unroll
    for (int i = 0; i < 2; i++) {
        int idx = tid + i * 512;
        int r = idx >> 2, ch = idx & 3;
        CP_ASYNC16(st + 2 * MG_AT + r * MG_RSTR + ch * 16,
                   (const void*)(Bh_ + (size_t)(bn + r) * K + koff + ch * 8));
        CP_ASYNC16(st + 2 * MG_AT + MG_BT + r * MG_RSTR + ch * 16,
                   (const void*)(Bl_ + (size_t)(bn + r) * K + koff + ch * 8));
    }
    CP_COMMIT();
}

template <bool BIAS_RELU, bool SPLIT>
__global__ void __launch_bounds__(512, 1) k_mma_gemm(
    const __half* __restrict__ Ahi, const __half* __restrict__ Alo,
    const __half* __restrict__ Bhi, const __half* __restrict__ Blo,
    const float* __restrict__ bias, float* __restrict__ Cf,
    __half2* __restrict__ Chi, __half2* __restrict__ Clo,
    int M, int N, int K) {
    extern __shared__ __align__(16) char smx[];
    const uint32_t sbase = smem_to_u32(smx);
    const int tid = threadIdx.x;
    const int lane = tid & 31;
    const int wid = tid >> 5;
    const int wm = (wid & 1) * 64;
    const int wn = (wid >> 1) * 32;
    const int bm = blockIdx.y * 128;
    const int bn = blockIdx.x * 256;

    const int CK = K / 32;

    float acc[4][4][4];
    #pragma unroll
    for (int i = 0; i < 4; i++)
        #pragma unroll
        for (int j = 0; j < 4; j++)
            #pragma unroll
            for (int q = 0; q < 4; q++) acc[i][j][q] = 0.f;

    mg_load4(Ahi, Alo, Bhi, Blo, M, K, bm, bn, 0, sbase, tid);
    if (CK > 1)
        mg_load4(Ahi, Alo, Bhi, Blo, M, K, bm, bn, 32, sbase + MG_ST4, tid);

    int sidx = 0;
    for (int c = 0; c < CK; c++) {
        if (c + 2 < CK) {
            int s2 = (sidx + 2) % 3;
            mg_load4(Ahi, Alo, Bhi, Blo, M, K, bm, bn, (c + 2) * 32,
                     sbase + s2 * MG_ST4, tid);
            CP_WAIT(2);
        } else if (c + 1 < CK) {
            CP_WAIT(1);
        } else {
            CP_WAIT(0);
        }
        __syncthreads();

        const uint32_t base = sbase + sidx * MG_ST4;
        #pragma unroll
        for (int kk = 0; kk < 32; kk += 16) {
            uint32_t ah[4][4], al[4][4];
            #pragma unroll
            for (int mi = 0; mi < 4; mi++) {
                int r = wm + mi * 16 + (lane & 15);
                int colb = (kk + ((lane >> 4) << 3)) * 2;
                LDSM_X4(ah[mi][0], ah[mi][1], ah[mi][2], ah[mi][3],
                        base + r * MG_RSTR + colb);
                LDSM_X4(al[mi][0], al[mi][1], al[mi][2], al[mi][3],
                        base + MG_AT + r * MG_RSTR + colb);
            }
            uint32_t bh[4][2], bl[4][2];
            #pragma unroll
            for (int nb = 0; nb < 2; nb++) {
                int n = wn + nb * 16 + (lane & 7) + ((lane >> 4) << 3);
                int colb = (kk + (((lane >> 3) & 1) << 3)) * 2;
                LDSM_X4(bh[2 * nb][0], bh[2 * nb][1], bh[2 * nb + 1][0], bh[2 * nb + 1][1],
                        base + 2 * MG_AT + n * MG_RSTR + colb);
                LDSM_X4(bl[2 * nb][0], bl[2 * nb][1], bl[2 * nb + 1][0], bl[2 * nb + 1][1],
                        base + 2 * MG_AT + MG_BT + n * MG_RSTR + colb);
            }
            #pragma unroll
            for (int mi = 0; mi < 4; mi++)
                #pragma unroll
                for (int nj = 0; nj < 4; nj++)
                    MMA_16816(acc[mi][nj], ah[mi], bh[nj]);
            #pragma unroll
            for (int mi = 0; mi < 4; mi++)
                #pragma unroll
                for (int nj = 0; nj < 4; nj++)
                    MMA_16816(acc[mi][nj], al[mi], bh[nj]);
            #pragma unroll
            for (int mi = 0; mi < 4; mi++)
                #pragma unroll
                for (int nj = 0; nj < 4; nj++)
                    MMA_16816(acc[mi][nj], ah[mi], bl[nj]);
        }
        __syncthreads();
        sidx = (sidx + 1) % 3;
    }

    // epilogue
    #pragma unroll
    for (int mi = 0; mi < 4; mi++) {
        int r0 = bm + wm + mi * 16 + (lane >> 2);
        #pragma unroll
        for (int nj = 0; nj < 4; nj++) {
            int cn = bn + wn + nj * 8 + (lane & 3) * 2;
            float2 v0, v1;
            v0.x = acc[mi][nj][0]; v0.y = acc[mi][nj][1];
            v1.x = acc[mi][nj][2]; v1.y = acc[mi][nj][3];
            if (BIAS_RELU) {
                float b0 = bias[cn], b1 = bias[cn + 1];
                v0.x = fmaxf(v0.x + b0, 0.f); v0.y = fmaxf(v0.y + b1, 0.f);
                v1.x = fmaxf(v1.x + b0, 0.f); v1.y = fmaxf(v1.y + b1, 0.f);
            }
            if (SPLIT) {
                #pragma unroll
                for (int rr = 0; rr < 2; rr++) {
                    int r = r0 + rr * 8;
                    if (r < M) {
                        float2 v = rr ? v1 : v0;
                        __half hx = __float2half(v.x), hy = __float2half(v.y);
                        __half lx = __float2half(v.x - __half2float(hx));
                        __half ly = __float2half(v.y - __half2float(hy));
                        size_t o = ((size_t)r * N + cn) >> 1;
                        Chi[o] = __halves2half2(hx, hy);
                        Clo[o] = __halves2half2(lx, ly);
                    }
                }
            } else {
                if (r0 < M)     *(float2*)(Cf + (size_t)r0 * N + cn) = v0;
                if (r0 + 8 < M) *(float2*)(Cf + (size_t)(r0 + 8) * N + cn) = v1;
            }
        }
    }
}

// ================= SIMT GEMM (small layers L1-L3) =================
template <bool RELU, bool BIAS>
__global__ void __launch_bounds__(256) k_gemm(
    const float* __restrict__ A, const float* __restrict__ B,
    const float* __restrict__ bias, float* __restrict__ C,
    int M, int N, int K) {
    constexpr int BMx = 128, BNx = 64, BK = 16, TM = 8, TN = 4;
    constexpr int AST = BMx + 4;
    __shared__ float As[BK * AST];
    __shared__ float Bs[BK * BNx];
    const int tid = threadIdx.x;
    const int bm = blockIdx.y * BMx;
    const int bn = blockIdx.x * BNx;
    const int tx = tid & 15;
    const int ty = tid >> 4;
    const int ar = tid >> 2;
    const int ac = (tid & 3) * 4;
    const int br = tid >> 4;
    const int bc = (tid & 15) * 4;
    float acc[TM][TN] = {};
    for (int kt = 0; kt < K; kt += BK) {
        #pragma unroll
        for (int i = 0; i < 2; i++) {
            int r = ar + i * 64;
            int gr = bm + r;
            float4 v = make_float4(0.f, 0.f, 0.f, 0.f);
            if (gr < M) v = *(const float4*)(A + (size_t)gr * K + kt + ac);
            As[(ac + 0) * AST + r] = v.x;
            As[(ac + 1) * AST + r] = v.y;
            As[(ac + 2) * AST + r] = v.z;
            As[(ac + 3) * AST + r] = v.w;
        }
        {
            float4 v = *(const float4*)(B + (size_t)(kt + br) * N + bn + bc);
            *(float4*)(Bs + br * BNx + bc) = v;
        }
        __syncthreads();
        #pragma unroll
        for (int k = 0; k < BK; k++) {
            float ra[TM], rb[TN];
            float4 a0 = *(const float4*)(As + k * AST + ty * TM);
            float4 a1 = *(const float4*)(As + k * AST + ty * TM + 4);
            ra[0] = a0.x; ra[1] = a0.y; ra[2] = a0.z; ra[3] = a0.w;
            ra[4] = a1.x; ra[5] = a1.y; ra[6] = a1.z; ra[7] = a1.w;
            float4 b0 = *(const float4*)(Bs + k * BNx + tx * TN);
            rb[0] = b0.x; rb[1] = b0.y; rb[2] = b0.z; rb[3] = b0.w;
            #pragma unroll
            for (int m = 0; m < TM; m++)
                #pragma unroll
                for (int n = 0; n < TN; n++)
                    acc[m][n] += ra[m] * rb[n];
        }
        __syncthreads();
    }
    float bv[TN] = {0.f, 0.f, 0.f, 0.f};
    if (BIAS) {
        float4 t = *(const float4*)(bias + bn + tx * TN);
        bv[0] = t.x; bv[1] = t.y; bv[2] = t.z; bv[3] = t.w;
    }
    #pragma unroll
    for (int m = 0; m < TM; m++) {
        int gr = bm + ty * TM + m;
        if (gr < M) {
            float4 o;
            o.x = acc[m][0] + bv[0];
            o.y = acc[m][1] + bv[1];
            o.z = acc[m][2] + bv[2];
            o.w = acc[m][3] + bv[3];
            if (RELU) {
                o.x = fmaxf(o.x, 0.f); o.y = fmaxf(o.y, 0.f);
                o.z = fmaxf(o.z, 0.f); o.w = fmaxf(o.w, 0.f);
            }
            *(float4*)(C + (size_t)gr * N + bn + tx * TN) = o;
        }
    }
}

// ================= host orchestration =================
extern "C" void kernel_launch(void* const* d_in, const int* in_sizes, int n_in,
                              void* d_out, int out_size) {
    const float* x = (const float*)d_in[0];
    const int* ei  = (const int*)d_in[1];
    const int* row = ei;
    const int* col = ei + EE;
    const float* W[8];
    const float* b[8];
    for (int i = 0; i < 8; i++) {
        W[i] = (const float*)d_in[2 + 2 * i];
        b[i] = (const float*)d_in[3 + 2 * i];
    }
    float *bufA, *bufB, *dis, *enrm;
    __half *Ahi, *Alo, *Bhi, *Blo, *Wh, *Wl;
    int *cnt, *cur, *off, *bsum, *src;
    cudaGetSymbolAddress((void**)&bufA, g_bufA);
    cudaGetSymbolAddress((void**)&bufB, g_bufB);
    cudaGetSymbolAddress((void**)&Ahi,  g_Ahi);
    cudaGetSymbolAddress((void**)&Alo,  g_Alo);
    cudaGetSymbolAddress((void**)&Bhi,  g_Bhi);
    cudaGetSymbolAddress((void**)&Blo,  g_Blo);
    cudaGetSymbolAddress((void**)&Wh,   g_Wh);
    cudaGetSymbolAddress((void**)&Wl,   g_Wl);
    cudaGetSymbolAddress((void**)&cnt,  g_cnt);
    cudaGetSymbolAddress((void**)&cur,  g_cur);
    cudaGetSymbolAddress((void**)&off,  g_off);
    cudaGetSymbolAddress((void**)&bsum, g_bsum);
    cudaGetSymbolAddress((void**)&dis,  g_dis);
    cudaGetSymbolAddress((void**)&src,  g_src);
    cudaGetSymbolAddress((void**)&enrm, g_enrm);
    float* out = (float*)d_out;

    cudaFuncSetAttribute(k_mma_gemm<true, true>,
                         cudaFuncAttributeMaxDynamicSharedMemorySize, MG_SMEM);
    cudaFuncSetAttribute(k_mma_gemm<false, false>,
                         cudaFuncAttributeMaxDynamicSharedMemorySize, MG_SMEM);

    // ---- CSR build + all weight splits ----
    cudaMemsetAsync(cnt, 0, NN * sizeof(int), 0);
    cudaMemsetAsync(cur, 0, NN * sizeof(int), 0);
    k_cnt<<<(EE + 255) / 256, 256>>>(col, cnt);
    k_scan1<<<SCAN_NB, SCAN_BS>>>(cnt, off, bsum);
    k_scan2<<<1, 128>>>(bsum);
    k_scan3<<<(NN + 255) / 256, 256>>>(off, bsum, cnt, dis);
    k_fill<<<(EE + 255) / 256, 256>>>(row, col, dis, off, cur, src, enrm);
    k_wsplit_all<<<(WTOT + 255) / 256, 256>>>(W[4], W[5], W[6], Wh, Wl);

    // ---- L0: 3 -> 64 (fully fused) ----
    k_l0_fused<<<(NN + 63) / 64, 256>>>(x, off, src, enrm, dis, W[0], b[0], bufB);

    // ---- L1-L3 (separate gather + SIMT GEMM; proven config) ----
    k_gather4<64, false, false, false><<<(NN * 16 + 255) / 256, 256>>>(
        (const float4*)bufB, off, src, enrm, dis, nullptr, (float4*)bufA, nullptr, nullptr);
    k_gemm<true, true><<<dim3(1, (NN + 127) / 128), 256>>>(bufA, W[1], b[1], bufB, NN, 64, 64);

    k_gather4<64, false, false, false><<<(NN * 16 + 255) / 256, 256>>>(
        (const float4*)bufB, off, src, enrm, dis, nullptr, (float4*)bufA, nullptr, nullptr);
    k_gemm<true, true><<<dim3(1, (NN + 127) / 128), 256>>>(bufA, W[2], b[2], bufB, NN, 64, 64);

    k_gather4<64, false, false, false><<<(NN * 16 + 255) / 256, 256>>>(
        (const float4*)bufB, off, src, enrm, dis, nullptr, (float4*)bufA, nullptr, nullptr);
    k_gemm<true, true><<<dim3(2, (NN + 127) / 128), 256>>>(bufA, W[3], b[3], bufB, NN, 128, 64);

    // ---- L4: 128 -> 1024 (gather->split, mma with bias+relu, split output) ----
    k_gather4<128, false, false, true><<<(NN * 32 + 255) / 256, 256>>>(
        (const float4*)bufB, off, src, enrm, dis, nullptr, nullptr, (__half2*)Ahi, (__half2*)Alo);
    k_mma_gemm<true, true><<<dim3(4, (NN + 127) / 128), 512, MG_SMEM>>>(
        Ahi, Alo, Wh + WOFF4, Wl + WOFF4, b[4], nullptr,
        (__half2*)Bhi, (__half2*)Blo, NN, 1024, 128);

    // ---- L5: 1024 -> 512 (mma fp32 out; gather fuses bias+relu+split) ----
    k_mma_gemm<false, false><<<dim3(2, (NN + 127) / 128), 512, MG_SMEM>>>(
        Bhi, Blo, Wh + WOFF5, Wl + WOFF5, nullptr, bufA, nullptr, nullptr, NN, 512, 1024);
    k_gather4<512, true, true, true><<<(NN * 128 + 255) / 256, 256>>>(
        (const float4*)bufA, off, src, enrm, dis, b[5], nullptr, (__half2*)Ahi, (__half2*)Alo);

    // ---- L6 mma -> fused (L6 gather + bias + relu + L7 GEMM) -> final gather ----
    k_mma_gemm<false, false><<<dim3(1, (NN + 127) / 128), 512, MG_SMEM>>>(
        Ahi, Alo, Wh + WOFF6, Wl + WOFF6, nullptr, bufB, nullptr, nullptr, NN, 256, 512);
    k_l6l7<<<NN / 4, 256>>>(
        (const float4*)bufB, off, src, enrm, dis, b[6], W[7], bufA);
    k_gather1<2, true><<<(NN * 2 + 255) / 256, 256>>>(bufA, off, src, enrm, dis, b[7], out);
}

// round 16
// speedup vs baseline: 1.0542x; 1.0036x over previous
#include <cuda_runtime.h>
#include <cuda_fp16.h>
#include <cstdint>
#include <math.h>

#define NN 50000
#define EE 200000
#define SCAN_BS 512
#define SCAN_NB 98          // ceil(NN/512)

// weight-split packing offsets (elements) inside g_Wh / g_Wl
#define WOFF4 0
#define WOFF5 131072        // 128*1024
#define WOFF6 655360        // +1024*512
#define WTOT  786432        // +512*256

// ---------------- scratch (static device globals; allocation-free) ----------------
__device__ float g_bufA[(size_t)NN * 1024];
__device__ float g_bufB[(size_t)NN * 1024];
__device__ __half g_Ahi[(size_t)NN * 1024];
__device__ __half g_Alo[(size_t)NN * 1024];
__device__ __half g_Bhi[(size_t)NN * 1024];
__device__ __half g_Blo[(size_t)NN * 1024];
__device__ __half g_Wh[WTOT];
__device__ __half g_Wl[WTOT];
__device__ int   g_cnt[NN];
__device__ int   g_cur[NN];
__device__ int   g_off[NN + 1];
__device__ int   g_bsum[SCAN_NB];
__device__ float g_dis[NN];
__device__ int   g_src[EE];
__device__ float g_enrm[EE];

// ================= PTX helpers (arch-generic: sm_80+) =================
__device__ __forceinline__ uint32_t smem_to_u32(const void* p) {
    uint32_t a;
    asm("{ .reg .u64 t; cvta.to.shared.u64 t, %1; cvt.u32.u64 %0, t; }" : "=r"(a) : "l"(p));
    return a;
}
#define CP_ASYNC16(dst, src) \
    asm volatile("cp.async.cg.shared.global [%0], [%1], 16;" :: "r"(dst), "l"(src))
#define CP_COMMIT() asm volatile("cp.async.commit_group;" ::: "memory")
#define CP_WAIT(n)  asm volatile("cp.async.wait_group %0;" :: "n"(n) : "memory")
#define LDSM_X4(r0, r1, r2, r3, addr) \
    asm volatile("ldmatrix.sync.aligned.m8n8.x4.shared.b16 {%0,%1,%2,%3}, [%4];" \
        : "=r"(r0), "=r"(r1), "=r"(r2), "=r"(r3) : "r"(addr))
#define MMA_16816(c, a, b) \
    asm volatile("mma.sync.aligned.m16n8k16.row.col.f32.f16.f16.f32 " \
        "{%0,%1,%2,%3}, {%4,%5,%6,%7}, {%8,%9}, {%0,%1,%2,%3};" \
        : "+f"((c)[0]), "+f"((c)[1]), "+f"((c)[2]), "+f"((c)[3]) \
        : "r"((a)[0]), "r"((a)[1]), "r"((a)[2]), "r"((a)[3]), "r"((b)[0]), "r"((b)[1]))

// ================= CSR build =================
__global__ void k_cnt(const int* __restrict__ col, int* __restrict__ cnt) {
    int e = blockIdx.x * blockDim.x + threadIdx.x;
    if (e < EE) atomicAdd(&cnt[col[e]], 1);
}
__global__ void k_scan1(const int* __restrict__ cnt, int* __restrict__ off,
                        int* __restrict__ bsum) {
    __shared__ int sh[SCAN_BS];
    int tid = threadIdx.x;
    int i = blockIdx.x * SCAN_BS + tid;
    int v = (i < NN) ? cnt[i] : 0;
    sh[tid] = v;
    __syncthreads();
    #pragma unroll
    for (int d = 1; d < SCAN_BS; d <<= 1) {
        int t = (tid >= d) ? sh[tid - d] : 0;
        __syncthreads();
        sh[tid] += t;
        __syncthreads();
    }
    if (i < NN) off[i] = sh[tid] - v;          // exclusive
    if (tid == SCAN_BS - 1) bsum[blockIdx.x] = sh[tid];
}
__global__ void k_scan2(int* __restrict__ bsum) {
    __shared__ int sh[128];
    int tid = threadIdx.x;
    int v = (tid < SCAN_NB) ? bsum[tid] : 0;
    sh[tid] = v;
    __syncthreads();
    #pragma unroll
    for (int d = 1; d < 128; d <<= 1) {
        int t = (tid >= d) ? sh[tid - d] : 0;
        __syncthreads();
        sh[tid] += t;
        __syncthreads();
    }
    if (tid < SCAN_NB) bsum[tid] = sh[tid] - v;  // exclusive
}
// also computes dis = rsqrt(deg)
__global__ void k_scan3(int* __restrict__ off, const int* __restrict__ bsum,
                        const int* __restrict__ cnt, float* __restrict__ dis) {
    int i = blockIdx.x * blockDim.x + threadIdx.x;
    if (i < NN) {
        off[i] += bsum[i / SCAN_BS];
        dis[i] = rsqrtf((float)(cnt[i] + 1));
    }
    if (i == 0) off[NN] = EE;
}
__global__ void k_fill(const int* __restrict__ row, const int* __restrict__ col,
                       const float* __restrict__ dis, const int* __restrict__ off,
                       int* __restrict__ cur, int* __restrict__ src,
                       float* __restrict__ enrm) {
    int e = blockIdx.x * blockDim.x + threadIdx.x;
    if (e >= EE) return;
    int r = row[e], c = col[e];
    int pos = off[c] + atomicAdd(&cur[c], 1);
    src[pos] = r;
    enrm[pos] = dis[r] * dis[c];
}

// ================= fused CSR gather aggregation =================
// Neighbor loop unrolled by 2 (MLP=2); accumulation order preserved exactly.
template <int F, bool BIAS, bool RELU, bool SPLIT>
__global__ void __launch_bounds__(256) k_gather4(
    const float4* __restrict__ h, const int* __restrict__ off,
    const int* __restrict__ src, const float* __restrict__ enrm,
    const float* __restrict__ dis, const float* __restrict__ bias,
    float4* __restrict__ outf, __half2* __restrict__ ohi, __half2* __restrict__ olo) {
    constexpr int FV = F / 4;
    int idx = blockIdx.x * blockDim.x + threadIdx.x;
    if (idx >= NN * FV) return;
    int i = idx / FV;
    int f4 = idx - i * FV;
    float d = dis[i];
    float s = d * d;
    float4 v = h[(size_t)i * FV + f4];
    float4 acc;
    acc.x = s * v.x; acc.y = s * v.y; acc.z = s * v.z; acc.w = s * v.w;
    int p0 = off[i], p1 = off[i + 1];
    int p = p0;
    for (; p + 1 < p1; p += 2) {
        int sn0 = src[p];
        int sn1 = src[p + 1];
        float w0 = enrm[p];
        float w1 = enrm[p + 1];
        float4 u0 = h[(size_t)sn0 * FV + f4];
        float4 u1 = h[(size_t)sn1 * FV + f4];
        acc.x += w0 * u0.x; acc.y += w0 * u0.y; acc.z += w0 * u0.z; acc.w += w0 * u0.w;
        acc.x += w1 * u1.x; acc.y += w1 * u1.y; acc.z += w1 * u1.z; acc.w += w1 * u1.w;
    }
    if (p < p1) {
        int sn = src[p];
        float w = enrm[p];
        float4 u = h[(size_t)sn * FV + f4];
        acc.x += w * u.x; acc.y += w * u.y; acc.z += w * u.z; acc.w += w * u.w;
    }
    if (BIAS) {
        const float4 bv = *(const float4*)(bias + f4 * 4);
        acc.x += bv.x; acc.y += bv.y; acc.z += bv.z; acc.w += bv.w;
    }
    if (RELU) {
        acc.x = fmaxf(acc.x, 0.f); acc.y = fmaxf(acc.y, 0.f);
        acc.z = fmaxf(acc.z, 0.f); acc.w = fmaxf(acc.w, 0.f);
    }
    if (SPLIT) {
        __half hx = __float2half(acc.x), hy = __float2half(acc.y);
        __half hz = __float2half(acc.z), hw = __float2half(acc.w);
        __half lx = __float2half(acc.x - __half2float(hx));
        __half ly = __float2half(acc.y - __half2float(hy));
        __half lz = __float2half(acc.z - __half2float(hz));
        __half lw = __float2half(acc.w - __half2float(hw));
        __half2 h01 = __halves2half2(hx, hy), h23 = __halves2half2(hz, hw);
        __half2 l01 = __halves2half2(lx, ly), l23 = __halves2half2(lz, lw);
        uint2 ph, pl;
        ph.x = *(uint32_t*)&h01; ph.y = *(uint32_t*)&h23;
        pl.x = *(uint32_t*)&l01; pl.y = *(uint32_t*)&l23;
        *(uint2*)(ohi + (size_t)idx * 2) = ph;
        *(uint2*)(olo + (size_t)idx * 2) = pl;
    } else {
        outf[idx] = acc;
    }
}

// scalar variant for F=2 (final layer)
template <int F, bool BIAS>
__global__ void k_gather1(const float* __restrict__ h, const int* __restrict__ off,
                          const int* __restrict__ src, const float* __restrict__ enrm,
                          const float* __restrict__ dis, const float* __restrict__ bias,
                          float* __restrict__ outf) {
    int idx = blockIdx.x * blockDim.x + threadIdx.x;
    if (idx >= NN * F) return;
    int i = idx / F;
    int f = idx - i * F;
    float d = dis[i];
    float acc = d * d * h[(size_t)i * F + f];
    int p0 = off[i], p1 = off[i + 1];
    for (int p = p0; p < p1; p++)
        acc += enrm[p] * h[(size_t)src[p] * F + f];
    if (BIAS) acc += bias[f];
    outf[idx] = acc;
}

// ================= fused L0: gather@3 + GEMM 3->64 + bias + relu =================
__global__ void __launch_bounds__(256) k_l0_fused(
    const float* __restrict__ x, const int* __restrict__ off,
    const int* __restrict__ src, const float* __restrict__ enrm,
    const float* __restrict__ dis, const float* __restrict__ W,
    const float* __restrict__ b, float* __restrict__ y) {
    __shared__ float sX[64][3];
    __shared__ float sW[3][64];
    __shared__ float sB[64];
    int tid = threadIdx.x;
    int bn0 = blockIdx.x * 64;
    if (tid < 192) sW[tid / 64][tid % 64] = W[tid];      // W is [3,64] row-major
    if (tid >= 192) sB[tid - 192] = b[tid - 192];
    if (tid < 192) {
        int n = tid / 3, f = tid - n * 3;
        int gi = bn0 + n;
        float acc = 0.f;
        if (gi < NN) {
            float d = dis[gi];
            acc = d * d * x[gi * 3 + f];
            int p0 = off[gi], p1 = off[gi + 1];
            for (int p = p0; p < p1; p++)
                acc += enrm[p] * x[src[p] * 3 + f];
        }
        sX[n][f] = acc;
    }
    __syncthreads();
    #pragma unroll
    for (int k = 0; k < 16; k++) {
        int o = tid + k * 256;
        int n = o >> 6, j = o & 63;
        int gi = bn0 + n;
        if (gi < NN) {
            float acc = sB[j] + sX[n][0] * sW[0][j] + sX[n][1] * sW[1][j]
                      + sX[n][2] * sW[2][j];
            y[(size_t)gi * 64 + j] = fmaxf(acc, 0.f);
        }
    }
}

// ================= fused L6-gather + L7-GEMM =================
// y[node, 0:2] = relu( A@(z6) + b6 )[node, 0:256] @ W7[256,2]
// 4 nodes/CTA, 64 threads/node (f4 = 0..63), warp-shuffle + smem reduce.
__global__ void __launch_bounds__(256) k_l6l7(
    const float4* __restrict__ h,       // z6 = x6@W6 (fp32, 256-wide, float4 view)
    const int* __restrict__ off, const int* __restrict__ src,
    const float* __restrict__ enrm, const float* __restrict__ dis,
    const float* __restrict__ b6, const float* __restrict__ W7,  // [256,2]
    float* __restrict__ y) {             // [NN,2]
    __shared__ float sW[512];
    __shared__ float sP[4][2][2];
    int tid = threadIdx.x;
    *(float2*)(sW + tid * 2) = *(const float2*)(W7 + tid * 2);
    __syncthreads();

    int idx = blockIdx.x * 256 + tid;
    int i = idx >> 6;          // node (grid sized so i < NN always)
    int f4 = idx & 63;
    // gather (identical math to k_gather4<256, BIAS=true>, unroll-2)
    float d = dis[i];
    float s = d * d;
    float4 v = h[(size_t)i * 64 + f4];
    float4 acc;
    acc.x = s * v.x; acc.y = s * v.y; acc.z = s * v.z; acc.w = s * v.w;
    int p0 = off[i], p1 = off[i + 1];
    int p = p0;
    for (; p + 1 < p1; p += 2) {
        int sn0 = src[p];
        int sn1 = src[p + 1];
        float w0 = enrm[p];
        float w1 = enrm[p + 1];
        float4 u0 = h[(size_t)sn0 * 64 + f4];
        float4 u1 = h[(size_t)sn1 * 64 + f4];
        acc.x += w0 * u0.x; acc.y += w0 * u0.y; acc.z += w0 * u0.z; acc.w += w0 * u0.w;
        acc.x += w1 * u1.x; acc.y += w1 * u1.y; acc.z += w1 * u1.z; acc.w += w1 * u1.w;
    }
    if (p < p1) {
        int sn = src[p];
        float w = enrm[p];
        float4 u = h[(size_t)sn * 64 + f4];
        acc.x += w * u.x; acc.y += w * u.y; acc.z += w * u.z; acc.w += w * u.w;
    }
    const float4 bv = *(const float4*)(b6 + f4 * 4);
    acc.x += bv.x; acc.y += bv.y; acc.z += bv.z; acc.w += bv.w;
    // relu + dot with W7
    float r0 = fmaxf(acc.x, 0.f), r1 = fmaxf(acc.y, 0.f);
    float r2 = fmaxf(acc.z, 0.f), r3 = fmaxf(acc.w, 0.f);
    int k0 = f4 * 4;
    float pa = r0 * sW[(k0 + 0) * 2 + 0] + r1 * sW[(k0 + 1) * 2 + 0]
             + r2 * sW[(k0 + 2) * 2 + 0] + r3 * sW[(k0 + 3) * 2 + 0];
    float pb = r0 * sW[(k0 + 0) * 2 + 1] + r1 * sW[(k0 + 1) * 2 + 1]
             + r2 * sW[(k0 + 2) * 2 + 1] + r3 * sW[(k0 + 3) * 2 + 1];
    #pragma unroll
    for (int o = 16; o > 0; o >>= 1) {
        pa += __shfl_down_sync(0xFFFFFFFFu, pa, o);
        pb += __shfl_down_sync(0xFFFFFFFFu, pb, o);
    }
    int lane = tid & 31;
    if (lane == 0) {
        int nb = tid >> 6;           // node in block (0..3)
        int wh = (tid >> 5) & 1;     // warp half
        sP[nb][wh][0] = pa;
        sP[nb][wh][1] = pb;
    }
    __syncthreads();
    if (tid < 8) {
        int n = tid >> 1, c = tid & 1;
        int gi = blockIdx.x * 4 + n;
        y[gi * 2 + c] = sP[n][0][c] + sP[n][1][c];
    }
}

// ================= combined weight split (W4+W5+W6 in one launch) =================
__global__ void k_wsplit_all(const float* __restrict__ W4, const float* __restrict__ W5,
                             const float* __restrict__ W6, __half* __restrict__ Wh,
                             __half* __restrict__ Wl) {
    int idx = blockIdx.x * blockDim.x + threadIdx.x;
    if (idx >= WTOT) return;
    const float* W; int K, N, li;
    if (idx < WOFF5)      { W = W4; K = 128;  N = 1024; li = idx; }
    else if (idx < WOFF6) { W = W5; K = 1024; N = 512;  li = idx - WOFF5; }
    else                  { W = W6; K = 512;  N = 256;  li = idx - WOFF6; }
    int n = li / K;
    int k = li - n * K;
    float v = W[(size_t)k * N + n];
    __half h = __float2half(v);
    Wh[idx] = h;
    Wl[idx] = __float2half(v - __half2float(h));
}

// ================= fused-product mma.sync split-fp16 GEMM =================
// C = AhWh + AlWh + AhWl (single K sweep).
// CTA tile 128x256, BK=32, 16 warps (2m x 8n), warp tile 64x32, 3-stage pipeline.
#define MG_RSTR  80
#define MG_AT    10240
#define MG_BT    20480
#define MG_ST4   61440
#define MG_SMEM  (3 * MG_ST4)

__device__ __forceinline__ void mg_load4(
    const __half* __restrict__ Ah_, const __half* __restrict__ Al_,
    const __half* __restrict__ Bh_, const __half* __restrict__ Bl_,
    int M, int K, int bm, int bn, int koff, uint32_t st, int tid) {
    {
        int r = tid >> 2, ch = tid & 3;
        int gr = bm + r;
        if (gr >= M) gr = M - 1;
        CP_ASYNC16(st + r * MG_RSTR + ch * 16,
                   (const void*)(Ah_ + (size_t)gr * K + koff + ch * 8));
        CP_ASYNC16(st + MG_AT + r * MG_RSTR + ch * 16,
                   (const void*)(Al_ + (size_t)gr * K + koff + ch * 8));
    }
    #pragma unroll
    for (int i = 0; i < 2; i++) {
        int idx = tid + i * 512;
        int r = idx >> 2, ch = idx & 3;
        CP_ASYNC16(st + 2 * MG_AT + r * MG_RSTR + ch * 16,
                   (const void*)(Bh_ + (size_t)(bn + r) * K + koff + ch * 8));
        CP_ASYNC16(st + 2 * MG_AT + MG_BT + r * MG_RSTR + ch * 16,
                   (const void*)(Bl_ + (size_t)(bn + r) * K + koff + ch * 8));
    }
    CP_COMMIT();
}

template <bool BIAS_RELU, bool SPLIT>
__global__ void __launch_bounds__(512, 1) k_mma_gemm(
    const __half* __restrict__ Ahi, const __half* __restrict__ Alo,
    const __half* __restrict__ Bhi, const __half* __restrict__ Blo,
    const float* __restrict__ bias, float* __restrict__ Cf,
    __half2* __restrict__ Chi, __half2* __restrict__ Clo,
    int M, int N, int K) {
    extern __shared__ __align__(16) char smx[];
    const uint32_t sbase = smem_to_u32(smx);
    const int tid = threadIdx.x;
    const int lane = tid & 31;
    const int wid = tid >> 5;
    const int wm = (wid & 1) * 64;
    const int wn = (wid >> 1) * 32;
    const int bm = blockIdx.y * 128;
    const int bn = blockIdx.x * 256;

    const int CK = K / 32;

    float acc[4][4][4];
    #pragma unroll
    for (int i = 0; i < 4; i++)
        #pragma unroll
        for (int j = 0; j < 4; j++)
            #pragma unroll
            for (int q = 0; q < 4; q++) acc[i][j][q] = 0.f;

    mg_load4(Ahi, Alo, Bhi, Blo, M, K, bm, bn, 0, sbase, tid);
    if (CK > 1)
        mg_load4(Ahi, Alo, Bhi, Blo, M, K, bm, bn, 32, sbase + MG_ST4, tid);

    int sidx = 0;
    for (int c = 0; c < CK; c++) {
        if (c + 2 < CK) {
            int s2 = (sidx + 2) % 3;
            mg_load4(Ahi, Alo, Bhi, Blo, M, K, bm, bn, (c + 2) * 32,
                     sbase + s2 * MG_ST4, tid);
            CP_WAIT(2);
        } else if (c + 1 < CK) {
            CP_WAIT(1);
        } else {
            CP_WAIT(0);
        }
        __syncthreads();

        const uint32_t base = sbase + sidx * MG_ST4;
        #pragma unroll
        for (int kk = 0; kk < 32; kk += 16) {
            uint32_t ah[4][4], al[4][4];
            #pragma unroll
            for (int mi = 0; mi < 4; mi++) {
                int r = wm + mi * 16 + (lane & 15);
                int colb = (kk + ((lane >> 4) << 3)) * 2;
                LDSM_X4(ah[mi][0], ah[mi][1], ah[mi][2], ah[mi][3],
                        base + r * MG_RSTR + colb);
                LDSM_X4(al[mi][0], al[mi][1], al[mi][2], al[mi][3],
                        base + MG_AT + r * MG_RSTR + colb);
            }
            uint32_t bh[4][2], bl[4][2];
            #pragma unroll
            for (int nb = 0; nb < 2; nb++) {
                int n = wn + nb * 16 + (lane & 7) + ((lane >> 4) << 3);
                int colb = (kk + (((lane >> 3) & 1) << 3)) * 2;
                LDSM_X4(bh[2 * nb][0], bh[2 * nb][1], bh[2 * nb + 1][0], bh[2 * nb + 1][1],
                        base + 2 * MG_AT + n * MG_RSTR + colb);
                LDSM_X4(bl[2 * nb][0], bl[2 * nb][1], bl[2 * nb + 1][0], bl[2 * nb + 1][1],
                        base + 2 * MG_AT + MG_BT + n * MG_RSTR + colb);
            }
            #pragma unroll
            for (int mi = 0; mi < 4; mi++)
                #pragma unroll
                for (int nj = 0; nj < 4; nj++)
                    MMA_16816(acc[mi][nj], ah[mi], bh[nj]);
            #pragma unroll
            for (int mi = 0; mi < 4; mi++)
                #pragma unroll
                for (int nj = 0; nj < 4; nj++)
                    MMA_16816(acc[mi][nj], al[mi], bh[nj]);
            #pragma unroll
            for (int mi = 0; mi < 4; mi++)
                #pragma unroll
                for (int nj = 0; nj < 4; nj++)
                    MMA_16816(acc[mi][nj], ah[mi], bl[nj]);
        }
        __syncthreads();
        sidx = (sidx + 1) % 3;
    }

    // epilogue
    #pragma unroll
    for (int mi = 0; mi < 4; mi++) {
        int r0 = bm + wm + mi * 16 + (lane >> 2);
        #pragma unroll
        for (int nj = 0; nj < 4; nj++) {
            int cn = bn + wn + nj * 8 + (lane & 3) * 2;
            float2 v0, v1;
            v0.x = acc[mi][nj][0]; v0.y = acc[mi][nj][1];
            v1.x = acc[mi][nj][2]; v1.y = acc[mi][nj][3];
            if (BIAS_RELU) {
                float b0 = bias[cn], b1 = bias[cn + 1];
                v0.x = fmaxf(v0.x + b0, 0.f); v0.y = fmaxf(v0.y + b1, 0.f);
                v1.x = fmaxf(v1.x + b0, 0.f); v1.y = fmaxf(v1.y + b1, 0.f);
            }
            if (SPLIT) {
                #pragma unroll
                for (int rr = 0; rr < 2; rr++) {
                    int r = r0 + rr * 8;
                    if (r < M) {
                        float2 v = rr ? v1 : v0;
                        __half hx = __float2half(v.x), hy = __float2half(v.y);
                        __half lx = __float2half(v.x - __half2float(hx));
                        __half ly = __float2half(v.y - __half2float(hy));
                        size_t o = ((size_t)r * N + cn) >> 1;
                        Chi[o] = __halves2half2(hx, hy);
                        Clo[o] = __halves2half2(lx, ly);
                    }
                }
            } else {
                if (r0 < M)     *(float2*)(Cf + (size_t)r0 * N + cn) = v0;
                if (r0 + 8 < M) *(float2*)(Cf + (size_t)(r0 + 8) * N + cn) = v1;
            }
        }
    }
}

// ================= SIMT GEMM (small layers L1-L3) =================
template <bool RELU, bool BIAS>
__global__ void __launch_bounds__(256) k_gemm(
    const float* __restrict__ A, const float* __restrict__ B,
    const float* __restrict__ bias, float* __restrict__ C,
    int M, int N, int K) {
    constexpr int BMx = 128, BNx = 64, BK = 16, TM = 8, TN = 4;
    constexpr int AST = BMx + 4;
    __shared__ float As[BK * AST];
    __shared__ float Bs[BK * BNx];
    const int tid = threadIdx.x;
    const int bm = blockIdx.y * BMx;
    const int bn = blockIdx.x * BNx;
    const int tx = tid & 15;
    const int ty = tid >> 4;
    const int ar = tid >> 2;
    const int ac = (tid & 3) * 4;
    const int br = tid >> 4;
    const int bc = (tid & 15) * 4;
    float acc[TM][TN] = {};
    for (int kt = 0; kt < K; kt += BK) {
        #pragma unroll
        for (int i = 0; i < 2; i++) {
            int r = ar + i * 64;
            int gr = bm + r;
            float4 v = make_float4(0.f, 0.f, 0.f, 0.f);
            if (gr < M) v = *(const float4*)(A + (size_t)gr * K + kt + ac);
            As[(ac + 0) * AST + r] = v.x;
            As[(ac + 1) * AST + r] = v.y;
            As[(ac + 2) * AST + r] = v.z;
            As[(ac + 3) * AST + r] = v.w;
        }
        {
            float4 v = *(const float4*)(B + (size_t)(kt + br) * N + bn + bc);
            *(float4*)(Bs + br * BNx + bc) = v;
        }
        __syncthreads();
        #pragma unroll
        for (int k = 0; k < BK; k++) {
            float ra[TM], rb[TN];
            float4 a0 = *(const float4*)(As + k * AST + ty * TM);
            float4 a1 = *(const float4*)(As + k * AST + ty * TM + 4);
            ra[0] = a0.x; ra[1] = a0.y; ra[2] = a0.z; ra[3] = a0.w;
            ra[4] = a1.x; ra[5] = a1.y; ra[6] = a1.z; ra[7] = a1.w;
            float4 b0 = *(const float4*)(Bs + k * BNx + tx * TN);
            rb[0] = b0.x; rb[1] = b0.y; rb[2] = b0.z; rb[3] = b0.w;
            #pragma unroll
            for (int m = 0; m < TM; m++)
                #pragma unroll
                for (int n = 0; n < TN; n++)
                    acc[m][n] += ra[m] * rb[n];
        }
        __syncthreads();
    }
    float bv[TN] = {0.f, 0.f, 0.f, 0.f};
    if (BIAS) {
        float4 t = *(const float4*)(bias + bn + tx * TN);
        bv[0] = t.x; bv[1] = t.y; bv[2] = t.z; bv[3] = t.w;
    }
    #pragma unroll
    for (int m = 0; m < TM; m++) {
        int gr = bm + ty * TM + m;
        if (gr < M) {
            float4 o;
            o.x = acc[m][0] + bv[0];
            o.y = acc[m][1] + bv[1];
            o.z = acc[m][2] + bv[2];
            o.w = acc[m][3] + bv[3];
            if (RELU) {
                o.x = fmaxf(o.x, 0.f); o.y = fmaxf(o.y, 0.f);
                o.z = fmaxf(o.z, 0.f); o.w = fmaxf(o.w, 0.f);
            }
            *(float4*)(C + (size_t)gr * N + bn + tx * TN) = o;
        }
    }
}

// ================= host orchestration =================
extern "C" void kernel_launch(void* const* d_in, const int* in_sizes, int n_in,
                              void* d_out, int out_size) {
    const float* x = (const float*)d_in[0];
    const int* ei  = (const int*)d_in[1];
    const int* row = ei;
    const int* col = ei + EE;
    const float* W[8];
    const float* b[8];
    for (int i = 0; i < 8; i++) {
        W[i] = (const float*)d_in[2 + 2 * i];
        b[i] = (const float*)d_in[3 + 2 * i];
    }
    float *bufA, *bufB, *dis, *enrm;
    __half *Ahi, *Alo, *Bhi, *Blo, *Wh, *Wl;
    int *cnt, *cur, *off, *bsum, *src;
    cudaGetSymbolAddress((void**)&bufA, g_bufA);
    cudaGetSymbolAddress((void**)&bufB, g_bufB);
    cudaGetSymbolAddress((void**)&Ahi,  g_Ahi);
    cudaGetSymbolAddress((void**)&Alo,  g_Alo);
    cudaGetSymbolAddress((void**)&Bhi,  g_Bhi);
    cudaGetSymbolAddress((void**)&Blo,  g_Blo);
    cudaGetSymbolAddress((void**)&Wh,   g_Wh);
    cudaGetSymbolAddress((void**)&Wl,   g_Wl);
    cudaGetSymbolAddress((void**)&cnt,  g_cnt);
    cudaGetSymbolAddress((void**)&cur,  g_cur);
    cudaGetSymbolAddress((void**)&off,  g_off);
    cudaGetSymbolAddress((void**)&bsum, g_bsum);
    cudaGetSymbolAddress((void**)&dis,  g_dis);
    cudaGetSymbolAddress((void**)&src,  g_src);
    cudaGetSymbolAddress((void**)&enrm, g_enrm);
    float* out = (float*)d_out;

    cudaFuncSetAttribute(k_mma_gemm<true, true>,
                         cudaFuncAttributeMaxDynamicSharedMemorySize, MG_SMEM);
    cudaFuncSetAttribute(k_mma_gemm<false, false>,
                         cudaFuncAttributeMaxDynamicSharedMemorySize, MG_SMEM);

    // ---- CSR build + all weight splits ----
    cudaMemsetAsync(cnt, 0, NN * sizeof(int), 0);
    cudaMemsetAsync(cur, 0, NN * sizeof(int), 0);
    k_cnt<<<(EE + 255) / 256, 256>>>(col, cnt);
    k_scan1<<<SCAN_NB, SCAN_BS>>>(cnt, off, bsum);
    k_scan2<<<1, 128>>>(bsum);
    k_scan3<<<(NN + 255) / 256, 256>>>(off, bsum, cnt, dis);
    k_fill<<<(EE + 255) / 256, 256>>>(row, col, dis, off, cur, src, enrm);
    k_wsplit_all<<<(WTOT + 255) / 256, 256>>>(W[4], W[5], W[6], Wh, Wl);

    // ---- L0: 3 -> 64 (fully fused) ----
    k_l0_fused<<<(NN + 63) / 64, 256>>>(x, off, src, enrm, dis, W[0], b[0], bufB);

    // ---- L1-L3 (separate gather + SIMT GEMM; proven config) ----
    k_gather4<64, false, false, false><<<(NN * 16 + 255) / 256, 256>>>(
        (const float4*)bufB, off, src, enrm, dis, nullptr, (float4*)bufA, nullptr, nullptr);
    k_gemm<true, true><<<dim3(1, (NN + 127) / 128), 256>>>(bufA, W[1], b[1], bufB, NN, 64, 64);

    k_gather4<64, false, false, false><<<(NN * 16 + 255) / 256, 256>>>(
        (const float4*)bufB, off, src, enrm, dis, nullptr, (float4*)bufA, nullptr, nullptr);
    k_gemm<true, true><<<dim3(1, (NN + 127) / 128), 256>>>(bufA, W[2], b[2], bufB, NN, 64, 64);

    k_gather4<64, false, false, false><<<(NN * 16 + 255) / 256, 256>>>(
        (const float4*)bufB, off, src, enrm, dis, nullptr, (float4*)bufA, nullptr, nullptr);
    k_gemm<true, true><<<dim3(2, (NN + 127) / 128), 256>>>(bufA, W[3], b[3], bufB, NN, 128, 64);

    // ---- L4: 128 -> 1024 (gather->split, mma with bias+relu, split output) ----
    k_gather4<128, false, false, true><<<(NN * 32 + 255) / 256, 256>>>(
        (const float4*)bufB, off, src, enrm, dis, nullptr, nullptr, (__half2*)Ahi, (__half2*)Alo);
    k_mma_gemm<true, true><<<dim3(4, (NN + 127) / 128), 512, MG_SMEM>>>(
        Ahi, Alo, Wh + WOFF4, Wl + WOFF4, b[4], nullptr,
        (__half2*)Bhi, (__half2*)Blo, NN, 1024, 128);

    // ---- L5: 1024 -> 512 (mma fp32 out; gather fuses bias+relu+split) ----
    k_mma_gemm<false, false><<<dim3(2, (NN + 127) / 128), 512, MG_SMEM>>>(
        Bhi, Blo, Wh + WOFF5, Wl + WOFF5, nullptr, bufA, nullptr, nullptr, NN, 512, 1024);
    k_gather4<512, true, true, true><<<(NN * 128 + 255) / 256, 256>>>(
        (const float4*)bufA, off, src, enrm, dis, b[5], nullptr, (__half2*)Ahi, (__half2*)Alo);

    // ---- L6 mma -> fused (L6 gather + bias + relu + L7 GEMM) -> final gather ----
    k_mma_gemm<false, false><<<dim3(1, (NN + 127) / 128), 512, MG_SMEM>>>(
        Ahi, Alo, Wh + WOFF6, Wl + WOFF6, nullptr, bufB, nullptr, nullptr, NN, 256, 512);
    k_l6l7<<<NN / 4, 256>>>(
        (const float4*)bufB, off, src, enrm, dis, b[6], W[7], bufA);
    k_gather1<2, true><<<(NN * 2 + 255) / 256, 256>>>(bufA, off, src, enrm, dis, b[7], out);
}